// round 9
// baseline (speedup 1.0000x reference)
#include <cuda_runtime.h>
#include <cuda_bf16.h>
#include <math.h>

// ---------------- problem constants ----------------
#define BATCH   8
#define SEQ     2048
#define HDIM    512
#define DPROJ   2192
#define DINNER  1024
#define DSTATE  64
#define NHEADS  16
#define HEADD   64
#define CONVD   1152
#define ML      (BATCH*SEQ)
#define EPSLN   1e-5f
#define CH      64
#define NCH     (SEQ/CH)

typedef unsigned long long u64;

// ---------------- device scratch ----------------
__device__ float g_x0 [ML*HDIM];
__device__ float g_h  [ML*HDIM];
__device__ float g_hf [ML*HDIM];
__device__ float g_zx0[ML*DPROJ];
__device__ float g_zx1[ML*DPROJ];
__device__ float g_xc0[ML*CONVD];
__device__ float g_xc1[ML*CONVD];
__device__ float g_dt0[ML*NHEADS];
__device__ float g_dt1[ML*NHEADS];
__device__ float g_y0 [ML*DINNER];
__device__ float g_y1 [ML*DINNER];
__device__ float g_d1 [ML*HDIM];
__device__ float g_cb [ML*DINNER];
__device__ float g_ot [ML*HDIM];
__device__ float g_pl [BATCH*2*HDIM];
__device__ float g_Sc [2*128*NCH*4096];
__device__ float g_Sin[2*128*NCH*4096];
__device__ float g_dec[2*128*NCH];

// ---------------- helpers ----------------
__device__ __forceinline__ unsigned int f2tf32(float v)
{
    unsigned int u;
    asm("cvt.rna.tf32.f32 %0, %1;" : "=r"(u) : "f"(v));
    return u;
}

__device__ __forceinline__ void mma_tf32(float c[4],
                                         unsigned a0, unsigned a1, unsigned a2, unsigned a3,
                                         unsigned b0, unsigned b1)
{
    asm volatile(
        "mma.sync.aligned.m16n8k8.row.col.f32.tf32.tf32.f32 "
        "{%0,%1,%2,%3}, {%4,%5,%6,%7}, {%8,%9}, {%0,%1,%2,%3};"
        : "+f"(c[0]), "+f"(c[1]), "+f"(c[2]), "+f"(c[3])
        : "r"(a0), "r"(a1), "r"(a2), "r"(a3), "r"(b0), "r"(b1));
}

__device__ __forceinline__ u64 fma2(u64 a, u64 b, u64 c)
{
    u64 d; asm("fma.rn.f32x2 %0,%1,%2,%3;" : "=l"(d) : "l"(a), "l"(b), "l"(c)); return d;
}
__device__ __forceinline__ u64 mul2(u64 a, u64 b)
{
    u64 d; asm("mul.rn.f32x2 %0,%1,%2;" : "=l"(d) : "l"(a), "l"(b)); return d;
}
__device__ __forceinline__ u64 pack2(float lo, float hi)
{
    u64 d; asm("mov.b64 %0,{%1,%2};" : "=l"(d) : "f"(lo), "f"(hi)); return d;
}
__device__ __forceinline__ float2 unpack2(u64 v)
{
    float2 r; asm("mov.b64 {%0,%1},%2;" : "=f"(r.x), "=f"(r.y) : "l"(v)); return r;
}

// ---------------- tf32 tensor-core GEMM, double-buffered, 1 sync/tile -----
// (round-6 configuration: GST=36, scalar fragment LDS, regs<=128, 2 CTA/SM)
#define GST 36
#define GSZ (128*GST)
#define GEMM_SMEM (4*GSZ*4)

__global__ __launch_bounds__(256) void tf32gemm(
    const float* __restrict__ A, const float* __restrict__ W,
    const float* __restrict__ bias, float* __restrict__ C,
    int M, int N, int K, int ldc)
{
    extern __shared__ __align__(16) unsigned int dsm[];

    const int tid  = threadIdx.x;
    const int lane = tid & 31;
    const int wid  = tid >> 5;
    const int wm   = (wid & 3) * 32;
    const int wn   = (wid >> 2) * 64;
    const int bm   = blockIdx.y * 128;
    const int bn   = blockIdx.x * 128;

    const int cm0 = tid >> 3;
    const int ckq = tid & 7;

    const int fr = lane >> 2;
    const int fc = lane & 3;

    float acc[2][8][4];
#pragma unroll
    for (int i = 0; i < 2; i++)
#pragma unroll
        for (int j = 0; j < 8; j++)
#pragma unroll
            for (int r = 0; r < 4; r++) acc[i][j][r] = 0.f;

    const int nk = K >> 5;
    float4 ar[4], wr[4];
    bool wvalid[4];
#pragma unroll
    for (int q = 0; q < 4; q++) wvalid[q] = (bn + cm0 + 32 * q) < N;

    const float* Abase = A + (size_t)(bm + cm0) * K + ckq * 4;
    const float* Wbase = W + (size_t)(bn + cm0) * K + ckq * 4;

    auto LOAD = [&](int t) {
        const float* Ap = Abase + t * 32;
        const float* Wp = Wbase + t * 32;
#pragma unroll
        for (int q = 0; q < 4; q++) {
            ar[q] = *(const float4*)(Ap + (size_t)(32 * q) * K);
            wr[q] = wvalid[q] ? *(const float4*)(Wp + (size_t)(32 * q) * K)
                              : make_float4(0.f, 0.f, 0.f, 0.f);
        }
    };
    auto STORE = [&](int buf) {
        unsigned int* Asb = dsm + buf * 2 * GSZ;
        unsigned int* Wsb = Asb + GSZ;
#pragma unroll
        for (int q = 0; q < 4; q++) {
            uint4 av = make_uint4(f2tf32(ar[q].x), f2tf32(ar[q].y), f2tf32(ar[q].z), f2tf32(ar[q].w));
            uint4 wv = make_uint4(f2tf32(wr[q].x), f2tf32(wr[q].y), f2tf32(wr[q].z), f2tf32(wr[q].w));
            *(uint4*)&Asb[(cm0 + 32 * q) * GST + ckq * 4] = av;
            *(uint4*)&Wsb[(cm0 + 32 * q) * GST + ckq * 4] = wv;
        }
    };

    LOAD(0);
    STORE(0);
    __syncthreads();

    for (int t = 0; t < nk; t++) {
        const int cur = t & 1;
        if (t + 1 < nk) LOAD(t + 1);

        const unsigned int* Ac = dsm + cur * 2 * GSZ;
        const unsigned int* Wc = Ac + GSZ;
#pragma unroll
        for (int ks = 0; ks < 4; ks++) {
            const int kk = ks * 8 + fc;
            unsigned b0[8], b1[8];
#pragma unroll
            for (int nf = 0; nf < 8; nf++) {
                int nrow = wn + nf * 8 + fr;
                b0[nf] = Wc[nrow * GST + kk];
                b1[nf] = Wc[nrow * GST + kk + 4];
            }
#pragma unroll
            for (int mf = 0; mf < 2; mf++) {
                int mrow = wm + mf * 16 + fr;
                unsigned a0 = Ac[mrow * GST + kk];
                unsigned a1 = Ac[(mrow + 8) * GST + kk];
                unsigned a2 = Ac[mrow * GST + kk + 4];
                unsigned a3 = Ac[(mrow + 8) * GST + kk + 4];
#pragma unroll
                for (int nf = 0; nf < 8; nf++)
                    mma_tf32(acc[mf][nf], a0, a1, a2, a3, b0[nf], b1[nf]);
            }
        }
        if (t + 1 < nk) STORE(cur ^ 1);
        __syncthreads();
    }

#pragma unroll
    for (int mf = 0; mf < 2; mf++) {
        int r0 = bm + wm + mf * 16 + fr;
#pragma unroll
        for (int nf = 0; nf < 8; nf++) {
            int cc = bn + wn + nf * 8 + 2 * fc;
            if (cc < N) {
                float bz0 = bias ? bias[cc] : 0.f;
                float bz1 = bias ? bias[cc + 1] : 0.f;
                float2 v0 = make_float2(acc[mf][nf][0] + bz0, acc[mf][nf][1] + bz1);
                float2 v1 = make_float2(acc[mf][nf][2] + bz0, acc[mf][nf][3] + bz1);
                *(float2*)&C[(size_t)r0 * ldc + cc] = v0;
                *(float2*)&C[(size_t)(r0 + 8) * ldc + cc] = v1;
            }
        }
    }
}

// ---------------- embedding gather ----------------
__global__ void gather_embed(const int* __restrict__ tok,
                             const float* __restrict__ emb,
                             float* __restrict__ x0)
{
    int x = blockIdx.x * 256 + threadIdx.x;
    int c = x & 511;
    int m = x >> 9;
    x0[x] = emb[(size_t)tok[m] * HDIM + c];
}

// ---------------- flip ----------------
__global__ void flip_kernel(const float* __restrict__ src, float* __restrict__ dst,
                            const int* __restrict__ lens)
{
    int x = blockIdx.x * 256 + threadIdx.x;
    int c = x & 511;
    int bl = x >> 9;
    int t = bl & (SEQ - 1);
    int b = bl >> 11;
    int len = lens[b];
    int tt = (t < len) ? (len - 1 - t) : t;
    dst[x] = src[((size_t)(b * SEQ + tt) << 9) + c];
}

// ---------------- depthwise conv (k=4), 4 timesteps per thread ------------
__global__ void conv_kernel(const float* __restrict__ zx, const float* __restrict__ w,
                            const float* __restrict__ bias, float* __restrict__ xc)
{
    int x = blockIdx.x * 256 + threadIdx.x;
    int c = x % CONVD;
    int r = x / CONVD;
    int tq = r & (SEQ / 4 - 1);
    int b  = r / (SEQ / 4);
    int t0 = tq * 4;
    const float* base = zx + ((size_t)(b * SEQ + t0)) * DPROJ + DINNER + c;
    float w0 = w[c*4], w1 = w[c*4+1], w2 = w[c*4+2], w3 = w[c*4+3], bs = bias[c];
    float v[7];
#pragma unroll
    for (int j = 0; j < 7; j++) {
        int tau = t0 - 3 + j;
        v[j] = (tau >= 0) ? base[(long)(j - 3) * DPROJ] : 0.f;
    }
#pragma unroll
    for (int tt = 0; tt < 4; tt++) {
        float a = bs + w0 * v[tt] + w1 * v[tt+1] + w2 * v[tt+2] + w3 * v[tt+3];
        xc[((size_t)(b * SEQ + t0 + tt)) * CONVD + c] = a / (1.f + __expf(-a));
    }
}

// ---------------- dt = softplus(dt_raw + bias) ----------------
__global__ void dt_kernel(const float* __restrict__ zx, const float* __restrict__ dtb,
                          float* __restrict__ dto)
{
    int x = blockIdx.x * 256 + threadIdx.x;
    int h = x & 15;
    int bl = x >> 4;
    float v = zx[(size_t)bl * DPROJ + (DINNER + CONVD) + h] + dtb[h];
    dto[x] = (v > 20.f) ? v : log1pf(__expf(v));
}

// ================= chunked SSM scan =================
// S1: per-chunk state contribution S_c[p][s] and chunk decay.
__global__ __launch_bounds__(128) void chunk_state_kernel(
    const float* __restrict__ xc0, const float* __restrict__ xc1,
    const float* __restrict__ dtp0, const float* __restrict__ dtp1,
    const float* __restrict__ Alog,
    float* __restrict__ Sc, float* __restrict__ dec)
{
    const int c  = blockIdx.x;
    const int bh = blockIdx.y;
    const int d  = blockIdx.z;
    const int b = bh >> 4, h = bh & 15;
    const float* xc  = d ? xc1 : xc0;
    const float* dtp = d ? dtp1 : dtp0;
    const int tid = threadIdx.x;
    const int t0 = c * CH;

    __shared__ float dts[CH], cA[CH], ws[CH];
    __shared__ __align__(8) float XW[CH][66];
    __shared__ __align__(8) float Bsm[CH][66];

    if (tid < CH) {
        float dtv = dtp[(size_t)(b * SEQ + t0 + tid) * NHEADS + h];
        dts[tid] = dtv;
        cA[tid]  = __expf(Alog[d * NHEADS + h]) * dtv;
    }
    __syncthreads();
    if (tid < 32) {
        float v0 = cA[tid], v1 = cA[tid + 32];
#pragma unroll
        for (int o = 1; o < 32; o <<= 1) {
            float u0 = __shfl_up_sync(0xffffffffu, v0, o);
            float u1 = __shfl_up_sync(0xffffffffu, v1, o);
            if (tid >= o) { v0 += u0; v1 += u1; }
        }
        float tot = __shfl_sync(0xffffffffu, v0, 31);
        cA[tid] = v0;
        cA[tid + 32] = v1 + tot;
    }
    __syncthreads();
    const float cAend = cA[CH - 1];
    if (tid < CH) ws[tid] = __expf(cA[tid] - cAend) * dts[tid];
    if (tid == 0) dec[((size_t)d * 128 + bh) * NCH + c] = __expf(-cAend);
    __syncthreads();

    const size_t rbase = (size_t)(b * SEQ + t0) * CONVD;
#pragma unroll
    for (int k = 0; k < 32; k++) {
        int i = k * 128 + tid;
        int tt = i >> 6, pp = i & 63;
        XW [tt][pp] = xc[rbase + (size_t)tt * CONVD + h * HEADD + pp] * ws[tt];
        Bsm[tt][pp] = xc[rbase + (size_t)tt * CONVD + DINNER + pp];
    }
    __syncthreads();

    const int pg = (tid >> 3) * 4;
    const int sg = (tid & 7) * 8;
    u64 acc[4][4];
#pragma unroll
    for (int a_ = 0; a_ < 4; a_++)
#pragma unroll
        for (int b_ = 0; b_ < 4; b_++) acc[a_][b_] = 0ull;

    for (int tt = 0; tt < CH; tt++) {
        float2 f01 = unpack2(*(const u64*)&XW[tt][pg]);
        float2 f23 = unpack2(*(const u64*)&XW[tt][pg + 2]);
        u64 ap[4] = { pack2(f01.x, f01.x), pack2(f01.y, f01.y),
                      pack2(f23.x, f23.x), pack2(f23.y, f23.y) };
        u64 b0 = *(const u64*)&Bsm[tt][sg];
        u64 b1 = *(const u64*)&Bsm[tt][sg + 2];
        u64 b2 = *(const u64*)&Bsm[tt][sg + 4];
        u64 b3 = *(const u64*)&Bsm[tt][sg + 6];
#pragma unroll
        for (int pi = 0; pi < 4; pi++) {
            acc[pi][0] = fma2(b0, ap[pi], acc[pi][0]);
            acc[pi][1] = fma2(b1, ap[pi], acc[pi][1]);
            acc[pi][2] = fma2(b2, ap[pi], acc[pi][2]);
            acc[pi][3] = fma2(b3, ap[pi], acc[pi][3]);
        }
    }

    size_t ob = (((size_t)d * 128 + bh) * NCH + c) * 4096;
#pragma unroll
    for (int pi = 0; pi < 4; pi++)
#pragma unroll
        for (int j = 0; j < 4; j++)
            *(u64*)&Sc[ob + (size_t)(pg + pi) * 64 + sg + 2 * j] = acc[pi][j];
}

// S2: sequential over 32 chunks; one float4 column per thread (262144 threads).
__global__ __launch_bounds__(256) void chunk_seq_kernel(
    const float* __restrict__ Sc, const float* __restrict__ dec,
    float* __restrict__ Sin)
{
    const int gid = blockIdx.x * 256 + threadIdx.x;   // 0 .. 262143
    const int bhd = gid >> 10;                        // d*128+bh
    const int off = gid & 1023;                       // float4 column
    float4 run = make_float4(0.f, 0.f, 0.f, 0.f);
    const float* dp = dec + bhd * NCH;
#pragma unroll 4
    for (int c = 0; c < NCH; c++) {
        size_t o = (((size_t)bhd * NCH + c) << 10) + off;   // float4 units
        *(float4*)&Sin[o * 4] = run;
        float4 s4 = *(const float4*)&Sc[o * 4];
        float dcv = dp[c];
        run.x = run.x * dcv + s4.x;
        run.y = run.y * dcv + s4.y;
        run.z = run.z * dcv + s4.z;
        run.w = run.w * dcv + s4.w;
    }
}

// S3: per-chunk output: inter (C@Sin^T, row-decayed) + intra ((W.G)@X) + D*x, gated.
#define S3_SMEM (5*CH*66*4)
__global__ __launch_bounds__(128) void chunk_out_kernel(
    const float* __restrict__ xc0, const float* __restrict__ xc1,
    const float* __restrict__ zx0, const float* __restrict__ zx1,
    const float* __restrict__ dtp0, const float* __restrict__ dtp1,
    const float* __restrict__ Alog, const float* __restrict__ Dp,
    const float* __restrict__ Sin,
    float* __restrict__ y0, float* __restrict__ y1)
{
    const int c  = blockIdx.x;
    const int bh = blockIdx.y;
    const int d  = blockIdx.z;
    const int b = bh >> 4, h = bh & 15;
    const float* xc  = d ? xc1 : xc0;
    const float* zx  = d ? zx1 : zx0;
    const float* dtp = d ? dtp1 : dtp0;
    float* y = d ? y1 : y0;
    const int tid = threadIdx.x;
    const int t0 = c * CH;

    extern __shared__ __align__(8) float sm[];
    float* CsT  = sm;
    float* BsT  = sm + 1 * CH * 66;
    float* Xs   = sm + 2 * CH * 66;
    float* SinT = sm + 3 * CH * 66;
    float* WGT  = sm + 4 * CH * 66;
    __shared__ float dts[CH], cA[CH], rowdec[CH];

    const int tr0 = (tid >> 3) * 4;
    const int p0  = (tid & 7) * 8;

    float4 zr[4][2];
    const size_t zrow = (size_t)(b * SEQ + t0);
#pragma unroll
    for (int ti = 0; ti < 4; ti++) {
        const float* zp = zx + (zrow + tr0 + ti) * DPROJ + h * HEADD + p0;
        zr[ti][0] = *(const float4*)zp;
        zr[ti][1] = *(const float4*)(zp + 4);
    }

    if (tid < CH) {
        float dtv = dtp[(size_t)(b * SEQ + t0 + tid) * NHEADS + h];
        dts[tid] = dtv;
        cA[tid]  = __expf(Alog[d * NHEADS + h]) * dtv;
    }
    __syncthreads();
    if (tid < 32) {
        float v0 = cA[tid], v1 = cA[tid + 32];
#pragma unroll
        for (int o = 1; o < 32; o <<= 1) {
            float u0 = __shfl_up_sync(0xffffffffu, v0, o);
            float u1 = __shfl_up_sync(0xffffffffu, v1, o);
            if (tid >= o) { v0 += u0; v1 += u1; }
        }
        float tot = __shfl_sync(0xffffffffu, v0, 31);
        cA[tid] = v0;
        cA[tid + 32] = v1 + tot;
    }
    __syncthreads();
    if (tid < CH) rowdec[tid] = __expf(-cA[tid]);

    const size_t rbase = (size_t)(b * SEQ + t0) * CONVD;
    const size_t sinb = (((size_t)d * 128 + bh) * NCH + c) * 4096;
#pragma unroll
    for (int k = 0; k < 32; k++) {
        int i = k * 128 + tid;
        int tt = i >> 6, pp = i & 63;
        Xs  [tt * 66 + pp] = xc[rbase + (size_t)tt * CONVD + h * HEADD + pp];
        BsT [pp * 66 + tt] = xc[rbase + (size_t)tt * CONVD + DINNER + pp];
        CsT [pp * 66 + tt] = xc[rbase + (size_t)tt * CONVD + DINNER + DSTATE + pp];
        SinT[pp * 66 + tt] = Sin[sinb + (size_t)tt * 64 + pp];
    }
    __syncthreads();

    u64 acc[4][4];
#pragma unroll
    for (int a_ = 0; a_ < 4; a_++)
#pragma unroll
        for (int b_ = 0; b_ < 4; b_++) acc[a_][b_] = 0ull;

    for (int s = 0; s < CH; s++) {
        float2 f01 = unpack2(*(const u64*)&CsT[s * 66 + tr0]);
        float2 f23 = unpack2(*(const u64*)&CsT[s * 66 + tr0 + 2]);
        u64 ap[4] = { pack2(f01.x, f01.x), pack2(f01.y, f01.y),
                      pack2(f23.x, f23.x), pack2(f23.y, f23.y) };
        u64 b0 = *(const u64*)&BsT[s * 66 + p0];
        u64 b1 = *(const u64*)&BsT[s * 66 + p0 + 2];
        u64 b2 = *(const u64*)&BsT[s * 66 + p0 + 4];
        u64 b3 = *(const u64*)&BsT[s * 66 + p0 + 6];
#pragma unroll
        for (int pi = 0; pi < 4; pi++) {
            acc[pi][0] = fma2(b0, ap[pi], acc[pi][0]);
            acc[pi][1] = fma2(b1, ap[pi], acc[pi][1]);
            acc[pi][2] = fma2(b2, ap[pi], acc[pi][2]);
            acc[pi][3] = fma2(b3, ap[pi], acc[pi][3]);
        }
    }

#pragma unroll
    for (int ti = 0; ti < 4; ti++) {
        int t = tr0 + ti;
        float cat = cA[t];
#pragma unroll
        for (int j = 0; j < 4; j++) {
            float2 g = unpack2(acc[ti][j]);
            int ta0 = p0 + 2 * j, ta1 = ta0 + 1;
            float w0 = (ta0 <= t) ? __expf(cA[ta0] - cat) * dts[ta0] : 0.f;
            float w1 = (ta1 <= t) ? __expf(cA[ta1] - cat) * dts[ta1] : 0.f;
            WGT[ta0 * 66 + t] = g.x * w0;
            WGT[ta1 * 66 + t] = g.y * w1;
        }
    }
    __syncthreads();

#pragma unroll
    for (int a_ = 0; a_ < 4; a_++)
#pragma unroll
        for (int b_ = 0; b_ < 4; b_++) acc[a_][b_] = 0ull;

    for (int s = 0; s < CH; s++) {
        float2 f01 = unpack2(*(const u64*)&CsT[s * 66 + tr0]);
        float2 f23 = unpack2(*(const u64*)&CsT[s * 66 + tr0 + 2]);
        u64 ap[4] = { pack2(f01.x, f01.x), pack2(f01.y, f01.y),
                      pack2(f23.x, f23.x), pack2(f23.y, f23.y) };
        u64 b0 = *(const u64*)&SinT[s * 66 + p0];
        u64 b1 = *(const u64*)&SinT[s * 66 + p0 + 2];
        u64 b2 = *(const u64*)&SinT[s * 66 + p0 + 4];
        u64 b3 = *(const u64*)&SinT[s * 66 + p0 + 6];
#pragma unroll
        for (int pi = 0; pi < 4; pi++) {
            acc[pi][0] = fma2(b0, ap[pi], acc[pi][0]);
            acc[pi][1] = fma2(b1, ap[pi], acc[pi][1]);
            acc[pi][2] = fma2(b2, ap[pi], acc[pi][2]);
            acc[pi][3] = fma2(b3, ap[pi], acc[pi][3]);
        }
    }
#pragma unroll
    for (int ti = 0; ti < 4; ti++) {
        u64 rd2 = pack2(rowdec[tr0 + ti], rowdec[tr0 + ti]);
#pragma unroll
        for (int j = 0; j < 4; j++) acc[ti][j] = mul2(acc[ti][j], rd2);
    }

    for (int tt = 0; tt < CH; tt++) {
        float2 f01 = unpack2(*(const u64*)&WGT[tt * 66 + tr0]);
        float2 f23 = unpack2(*(const u64*)&WGT[tt * 66 + tr0 + 2]);
        u64 ap[4] = { pack2(f01.x, f01.x), pack2(f01.y, f01.y),
                      pack2(f23.x, f23.x), pack2(f23.y, f23.y) };
        u64 b0 = *(const u64*)&Xs[tt * 66 + p0];
        u64 b1 = *(const u64*)&Xs[tt * 66 + p0 + 2];
        u64 b2 = *(const u64*)&Xs[tt * 66 + p0 + 4];
        u64 b3 = *(const u64*)&Xs[tt * 66 + p0 + 6];
#pragma unroll
        for (int pi = 0; pi < 4; pi++) {
            acc[pi][0] = fma2(b0, ap[pi], acc[pi][0]);
            acc[pi][1] = fma2(b1, ap[pi], acc[pi][1]);
            acc[pi][2] = fma2(b2, ap[pi], acc[pi][2]);
            acc[pi][3] = fma2(b3, ap[pi], acc[pi][3]);
        }
    }

    const float Dv = Dp[d * NHEADS + h];
#pragma unroll
    for (int ti = 0; ti < 4; ti++) {
        int t = tr0 + ti;
        float out[8];
#pragma unroll
        for (int j = 0; j < 4; j++) {
            float2 a2 = unpack2(acc[ti][j]);
            out[2*j]   = a2.x + Dv * Xs[t * 66 + p0 + 2*j];
            out[2*j+1] = a2.y + Dv * Xs[t * 66 + p0 + 2*j + 1];
        }
        const float* zv = (const float*)&zr[ti][0];
#pragma unroll
        for (int e = 0; e < 8; e++) {
            float z = zv[e];
            out[e] *= z / (1.f + __expf(-z));
        }
        float* yp = y + (size_t)(b * SEQ + t0 + t) * DINNER + h * HEADD + p0;
        *(float4*)yp       = make_float4(out[0], out[1], out[2], out[3]);
        *(float4*)(yp + 4) = make_float4(out[4], out[5], out[6], out[7]);
    }
}

// ---------------- RMSNorm ----------------
__global__ __launch_bounds__(256) void rmsnorm_kernel(float* __restrict__ y,
                                                      const float* __restrict__ w)
{
    int row = blockIdx.x;
    float* p = y + (size_t)row * DINNER;
    int tid = threadIdx.x;
    float v[4];
    float ss = 0.f;
#pragma unroll
    for (int i = 0; i < 4; i++) { v[i] = p[tid + i * 256]; ss += v[i] * v[i]; }
#pragma unroll
    for (int o = 16; o; o >>= 1) ss += __shfl_xor_sync(0xffffffffu, ss, o);
    __shared__ float red[8];
    if ((tid & 31) == 0) red[tid >> 5] = ss;
    __syncthreads();
    float tot = 0.f;
#pragma unroll
    for (int i = 0; i < 8; i++) tot += red[i];
    float sc = rsqrtf(tot * (1.f / DINNER) + EPSLN);
#pragma unroll
    for (int i = 0; i < 4; i++)
        p[tid + i * 256] = v[i] * sc * w[tid + i * 256];
}

// ---------------- flip-cat ----------------
__global__ void flipcat_kernel(const float* __restrict__ bwd,
                               const int* __restrict__ lens, float* __restrict__ comb)
{
    int x = blockIdx.x * 256 + threadIdx.x;
    int c = x & 511;
    int bl = x >> 9;
    int t = bl & (SEQ - 1);
    int b = bl >> 11;
    int len = lens[b];
    int tt = (t < len) ? (len - 1 - t) : t;
    comb[(size_t)bl * DINNER + HDIM + c] = bwd[((size_t)(b * SEQ + tt)) * HDIM + c];
}

// ---------------- add + layernorm ----------------
__global__ __launch_bounds__(128) void addln_kernel(const float* __restrict__ out,
                                                    float* __restrict__ h,
                                                    const float* __restrict__ g,
                                                    const float* __restrict__ bta)
{
    int row = blockIdx.x;
    const float* po = out + (size_t)row * HDIM;
    float* ph = h + (size_t)row * HDIM;
    int tid = threadIdx.x;
    float v[4];
    float sum = 0.f;
#pragma unroll
    for (int i = 0; i < 4; i++) { v[i] = po[tid + i * 128] + ph[tid + i * 128]; sum += v[i]; }
#pragma unroll
    for (int o = 16; o; o >>= 1) sum += __shfl_xor_sync(0xffffffffu, sum, o);
    __shared__ float red[4];
    if ((tid & 31) == 0) red[tid >> 5] = sum;
    __syncthreads();
    float mean = (red[0] + red[1] + red[2] + red[3]) * (1.f / HDIM);
    float vs = 0.f;
#pragma unroll
    for (int i = 0; i < 4; i++) { float dd = v[i] - mean; vs += dd * dd; }
#pragma unroll
    for (int o = 16; o; o >>= 1) vs += __shfl_xor_sync(0xffffffffu, vs, o);
    __syncthreads();
    if ((tid & 31) == 0) red[tid >> 5] = vs;
    __syncthreads();
    float var = (red[0] + red[1] + red[2] + red[3]) * (1.f / HDIM);
    float sc = rsqrtf(var + EPSLN);
#pragma unroll
    for (int i = 0; i < 4; i++) {
        int c = tid + i * 128;
        ph[c] = (v[i] - mean) * sc * g[c] + bta[c];
    }
}

// ---------------- masked mean pool ----------------
__global__ __launch_bounds__(256) void pool_kernel(const float* __restrict__ enc,
                                                   const int* __restrict__ lens,
                                                   float* __restrict__ pooled)
{
    int b  = blockIdx.x >> 5;
    int c0 = (blockIdx.x & 31) * 32;
    int c  = threadIdx.x & 31;
    int ts = threadIdx.x >> 5;
    int len = lens[b];
    float s = 0.f;
    for (int t = ts; t < len; t += 8)
        s += enc[((size_t)(b * SEQ + t)) * (2 * HDIM) + c0 + c];
    __shared__ float red[8][32];
    red[ts][c] = s;
    __syncthreads();
    if (ts == 0) {
        float tot = 0.f;
#pragma unroll
        for (int i = 0; i < 8; i++) tot += red[i][c];
        pooled[b * (2 * HDIM) + c0 + c] = tot / (float)(len > 0 ? len : 1);
    }
}

// ---------------- adapter ----------------
__global__ __launch_bounds__(256) void adapter_kernel(const float* __restrict__ pooled,
                                                      const float* __restrict__ Wad,
                                                      const float* __restrict__ bad,
                                                      float* __restrict__ out)
{
    int w = blockIdx.x * 8 + (threadIdx.x >> 5);
    int lane = threadIdx.x & 31;
    int o = w & 511, b = w >> 9;
    const float* pr = pooled + (size_t)b * (2 * HDIM);
    const float* wr = Wad + (size_t)o * (2 * HDIM);
    float s = 0.f;
    for (int i = lane; i < 2 * HDIM; i += 32) s += pr[i] * wr[i];
#pragma unroll
    for (int off = 16; off; off >>= 1) s += __shfl_xor_sync(0xffffffffu, s, off);
    if (lane == 0) out[b * HDIM + o] = tanhf(s + bad[o]);
}

// ---------------- host ----------------
static float* symaddr(const void* s)
{
    void* p = nullptr;
    cudaGetSymbolAddress(&p, s);
    return (float*)p;
}

static inline dim3 ggrid(int N) { return dim3((N + 127) / 128, ML / 128); }

extern "C" void kernel_launch(void* const* d_in, const int* in_sizes, int n_in,
                              void* d_out, int out_size)
{
    const int*   tok    = (const int*)  d_in[0];
    const int*   lens   = (const int*)  d_in[1];
    const float* emb    = (const float*)d_in[2];
    const float* W_inp  = (const float*)d_in[3];
    const float* b_inp  = (const float*)d_in[4];
    const float* m_Win  = (const float*)d_in[5];
    const float* m_cw   = (const float*)d_in[6];
    const float* m_cb   = (const float*)d_in[7];
    const float* m_dtb  = (const float*)d_in[8];
    const float* m_Alog = (const float*)d_in[9];
    const float* m_D    = (const float*)d_in[10];
    const float* m_norm = (const float*)d_in[11];
    const float* m_Wout = (const float*)d_in[12];
    const float* blk_Wo = (const float*)d_in[13];
    const float* blk_bo = (const float*)d_in[14];
    const float* ln_g   = (const float*)d_in[15];
    const float* ln_b   = (const float*)d_in[16];
    const float* W_enc  = (const float*)d_in[17];
    const float* b_enc  = (const float*)d_in[18];
    const float* W_ad   = (const float*)d_in[19];
    const float* b_ad   = (const float*)d_in[20];
    float* outp = (float*)d_out;

    float* x0  = symaddr(g_x0);
    float* h   = symaddr(g_h);
    float* hf  = symaddr(g_hf);
    float* zx0 = symaddr(g_zx0);
    float* zx1 = symaddr(g_zx1);
    float* xc0 = symaddr(g_xc0);
    float* xc1 = symaddr(g_xc1);
    float* dt0 = symaddr(g_dt0);
    float* dt1 = symaddr(g_dt1);
    float* y0  = symaddr(g_y0);
    float* y1  = symaddr(g_y1);
    float* dr1 = symaddr(g_d1);
    float* cb  = symaddr(g_cb);
    float* ot  = symaddr(g_ot);
    float* pl  = symaddr(g_pl);
    float* Sc  = symaddr(g_Sc);
    float* Sin = symaddr(g_Sin);
    float* dec = symaddr(g_dec);

    static int smem_set = 0;
    if (!smem_set) {
        cudaFuncSetAttribute(tf32gemm, cudaFuncAttributeMaxDynamicSharedMemorySize, GEMM_SMEM);
        cudaFuncSetAttribute(chunk_out_kernel, cudaFuncAttributeMaxDynamicSharedMemorySize, S3_SMEM);
        smem_set = 1;
    }

    const int TPB = 256;
    dim3 gEl(ML * HDIM / TPB);
    dim3 gConv((ML / 4) * CONVD / TPB);
    dim3 gDt((ML * NHEADS) / TPB);

    gather_embed<<<gEl, TPB>>>(tok, emb, x0);
    tf32gemm<<<ggrid(HDIM), 256, GEMM_SMEM>>>(x0, W_inp, b_inp, h, ML, HDIM, HDIM, HDIM);

    for (int i = 0; i < 4; i++) {
        flip_kernel<<<gEl, TPB>>>(h, hf, lens);

        tf32gemm<<<ggrid(DPROJ), 256, GEMM_SMEM>>>(
            h,  m_Win + (size_t)(i * 2 + 0) * DPROJ * HDIM, nullptr, zx0, ML, DPROJ, HDIM, DPROJ);
        tf32gemm<<<ggrid(DPROJ), 256, GEMM_SMEM>>>(
            hf, m_Win + (size_t)(i * 2 + 1) * DPROJ * HDIM, nullptr, zx1, ML, DPROJ, HDIM, DPROJ);

        conv_kernel<<<gConv, TPB>>>(zx0, m_cw + (size_t)(i * 2 + 0) * CONVD * 4,
                                    m_cb + (size_t)(i * 2 + 0) * CONVD, xc0);
        conv_kernel<<<gConv, TPB>>>(zx1, m_cw + (size_t)(i * 2 + 1) * CONVD * 4,
                                    m_cb + (size_t)(i * 2 + 1) * CONVD, xc1);

        dt_kernel<<<gDt, TPB>>>(zx0, m_dtb + (i * 2 + 0) * NHEADS, dt0);
        dt_kernel<<<gDt, TPB>>>(zx1, m_dtb + (i * 2 + 1) * NHEADS, dt1);

        chunk_state_kernel<<<dim3(NCH, 128, 2), 128>>>(
            xc0, xc1, dt0, dt1, m_Alog + i * 2 * NHEADS, Sc, dec);
        chunk_seq_kernel<<<1024, 256>>>(Sc, dec, Sin);
        chunk_out_kernel<<<dim3(NCH, 128, 2), 128, S3_SMEM>>>(
            xc0, xc1, zx0, zx1, dt0, dt1,
            m_Alog + i * 2 * NHEADS, m_D + i * 2 * NHEADS, Sin, y0, y1);

        rmsnorm_kernel<<<ML, 256>>>(y0, m_norm + (size_t)(i * 2 + 0) * DINNER);
        rmsnorm_kernel<<<ML, 256>>>(y1, m_norm + (size_t)(i * 2 + 1) * DINNER);

        tf32gemm<<<ggrid(HDIM), 256, GEMM_SMEM>>>(
            y0, m_Wout + (size_t)(i * 2 + 0) * HDIM * DINNER, nullptr, cb, ML, HDIM, DINNER, DINNER);
        tf32gemm<<<ggrid(HDIM), 256, GEMM_SMEM>>>(
            y1, m_Wout + (size_t)(i * 2 + 1) * HDIM * DINNER, nullptr, dr1, ML, HDIM, DINNER, HDIM);

        flipcat_kernel<<<gEl, TPB>>>(dr1, lens, cb);
        tf32gemm<<<ggrid(HDIM), 256, GEMM_SMEM>>>(
            cb, blk_Wo + (size_t)i * HDIM * DINNER, blk_bo + i * HDIM, ot, ML, HDIM, DINNER, HDIM);
        addln_kernel<<<ML, 128>>>(ot, h, ln_g + i * HDIM, ln_b + i * HDIM);
    }

    tf32gemm<<<ggrid(2 * HDIM), 256, GEMM_SMEM>>>(h, W_enc, b_enc, outp, ML, 2 * HDIM, HDIM, 2 * HDIM);

    pool_kernel<<<BATCH * 32, 256>>>(outp, lens, pl);
    adapter_kernel<<<(BATCH * HDIM) / 8, 256>>>(pl, W_ad, b_ad,
                                                outp + (size_t)ML * 2 * HDIM);
}

// round 14
// speedup vs baseline: 1.0442x; 1.0442x over previous
#include <cuda_runtime.h>
#include <cuda_bf16.h>
#include <math.h>

// ---------------- problem constants ----------------
#define BATCH   8
#define SEQ     2048
#define HDIM    512
#define DPROJ   2192
#define DINNER  1024
#define DSTATE  64
#define NHEADS  16
#define HEADD   64
#define CONVD   1152
#define ML      (BATCH*SEQ)
#define EPSLN   1e-5f
#define CH      64
#define NCH     (SEQ/CH)

typedef unsigned long long u64;

// ---------------- device scratch ----------------
__device__ float g_x0 [ML*HDIM];
__device__ float g_h  [ML*HDIM];
__device__ float g_zx0[ML*DPROJ];
__device__ float g_zx1[ML*DPROJ];
__device__ float g_xc0[ML*CONVD];
__device__ float g_xc1[ML*CONVD];
__device__ float g_dt0[ML*NHEADS];
__device__ float g_dt1[ML*NHEADS];
__device__ float g_y0 [ML*DINNER];
__device__ float g_y1 [ML*DINNER];
__device__ float g_cb [ML*DINNER];
__device__ float g_ot [ML*HDIM];
__device__ float g_pl [BATCH*2*HDIM];
__device__ float g_Sc [2*128*NCH*4096];
__device__ float g_Sin[2*128*NCH*4096];
__device__ float g_dec[2*128*NCH];

// ---------------- helpers ----------------
__device__ __forceinline__ unsigned int f2tf32(float v)
{
    unsigned int u;
    asm("cvt.rna.tf32.f32 %0, %1;" : "=r"(u) : "f"(v));
    return u;
}

__device__ __forceinline__ void mma_tf32(float c[4],
                                         unsigned a0, unsigned a1, unsigned a2, unsigned a3,
                                         unsigned b0, unsigned b1)
{
    asm volatile(
        "mma.sync.aligned.m16n8k8.row.col.f32.tf32.tf32.f32 "
        "{%0,%1,%2,%3}, {%4,%5,%6,%7}, {%8,%9}, {%0,%1,%2,%3};"
        : "+f"(c[0]), "+f"(c[1]), "+f"(c[2]), "+f"(c[3])
        : "r"(a0), "r"(a1), "r"(a2), "r"(a3), "r"(b0), "r"(b1));
}

__device__ __forceinline__ u64 fma2(u64 a, u64 b, u64 c)
{
    u64 d; asm("fma.rn.f32x2 %0,%1,%2,%3;" : "=l"(d) : "l"(a), "l"(b), "l"(c)); return d;
}
__device__ __forceinline__ u64 mul2(u64 a, u64 b)
{
    u64 d; asm("mul.rn.f32x2 %0,%1,%2;" : "=l"(d) : "l"(a), "l"(b)); return d;
}
__device__ __forceinline__ u64 pack2(float lo, float hi)
{
    u64 d; asm("mov.b64 %0,{%1,%2};" : "=l"(d) : "f"(lo), "f"(hi)); return d;
}
__device__ __forceinline__ float2 unpack2(u64 v)
{
    float2 r; asm("mov.b64 {%0,%1},%2;" : "=f"(r.x), "=f"(r.y) : "l"(v)); return r;
}

// ---------------- tf32 tensor-core GEMM, double-buffered, 1 sync/tile -----
// blockIdx.z picks (A,W,C); optional length-flip on A rows (z=1) and/or on
// C rows (z=1). Flip map: within batch b, t -> (t<len)? len-1-t : t.
#define GST 36
#define GSZ (128*GST)
#define GEMM_SMEM (4*GSZ*4)

__global__ __launch_bounds__(256, 2) void tf32gemm(
    const float* __restrict__ A0, const float* __restrict__ A1,
    const float* __restrict__ W0, const float* __restrict__ W1,
    const float* __restrict__ bias,
    float* __restrict__ C0, float* __restrict__ C1,
    int M, int N, int K, int ldc,
    const int* __restrict__ lens, int flipA1, int flipOut1)
{
    extern __shared__ __align__(16) unsigned int dsm[];

    const int z = blockIdx.z;
    const float* A = z ? A1 : A0;
    const float* W = z ? W1 : W0;
    float* C = z ? C1 : C0;

    const int tid  = threadIdx.x;
    const int lane = tid & 31;
    const int wid  = tid >> 5;
    const int wm   = (wid & 3) * 32;
    const int wn   = (wid >> 2) * 64;
    const int bm   = blockIdx.y * 128;
    const int bn   = blockIdx.x * 128;

    const int cm0 = tid >> 3;
    const int ckq = tid & 7;

    const int fr = lane >> 2;
    const int fc = lane & 3;

    const int blen = lens ? lens[bm >> 11] : 0;   // all 128 rows share b
    const bool fA  = (z && flipA1);
    const bool fO  = (z && flipOut1);

    float acc[2][8][4];
#pragma unroll
    for (int i = 0; i < 2; i++)
#pragma unroll
        for (int j = 0; j < 8; j++)
#pragma unroll
            for (int r = 0; r < 4; r++) acc[i][j][r] = 0.f;

    const int nk = K >> 5;
    float4 ar[4], wr[4];
    bool wvalid[4];
    const float* Aq[4];
#pragma unroll
    for (int q = 0; q < 4; q++) {
        wvalid[q] = (bn + cm0 + 32 * q) < N;
        int m = bm + cm0 + 32 * q;
        if (fA) {
            int t = m & (SEQ - 1);
            int mb = m & ~(SEQ - 1);
            t = (t < blen) ? (blen - 1 - t) : t;
            m = mb + t;
        }
        Aq[q] = A + (size_t)m * K + ckq * 4;
    }
    const float* Wbase = W + (size_t)(bn + cm0) * K + ckq * 4;

    auto LOAD = [&](int t) {
#pragma unroll
        for (int q = 0; q < 4; q++) {
            ar[q] = *(const float4*)(Aq[q] + t * 32);
            wr[q] = wvalid[q] ? *(const float4*)(Wbase + (size_t)(32 * q) * K + t * 32)
                              : make_float4(0.f, 0.f, 0.f, 0.f);
        }
    };
    auto STORE = [&](int buf) {
        unsigned int* Asb = dsm + buf * 2 * GSZ;
        unsigned int* Wsb = Asb + GSZ;
#pragma unroll
        for (int q = 0; q < 4; q++) {
            uint4 av = make_uint4(f2tf32(ar[q].x), f2tf32(ar[q].y), f2tf32(ar[q].z), f2tf32(ar[q].w));
            uint4 wv = make_uint4(f2tf32(wr[q].x), f2tf32(wr[q].y), f2tf32(wr[q].z), f2tf32(wr[q].w));
            *(uint4*)&Asb[(cm0 + 32 * q) * GST + ckq * 4] = av;
            *(uint4*)&Wsb[(cm0 + 32 * q) * GST + ckq * 4] = wv;
        }
    };

    LOAD(0);
    STORE(0);
    __syncthreads();

    for (int t = 0; t < nk; t++) {
        const int cur = t & 1;
        if (t + 1 < nk) LOAD(t + 1);

        const unsigned int* Ac = dsm + cur * 2 * GSZ;
        const unsigned int* Wc = Ac + GSZ;
#pragma unroll
        for (int ks = 0; ks < 4; ks++) {
            const int kk = ks * 8 + fc;
            unsigned b0[8], b1[8];
#pragma unroll
            for (int nf = 0; nf < 8; nf++) {
                int nrow = wn + nf * 8 + fr;
                b0[nf] = Wc[nrow * GST + kk];
                b1[nf] = Wc[nrow * GST + kk + 4];
            }
#pragma unroll
            for (int mf = 0; mf < 2; mf++) {
                int mrow = wm + mf * 16 + fr;
                unsigned a0 = Ac[mrow * GST + kk];
                unsigned a1 = Ac[(mrow + 8) * GST + kk];
                unsigned a2 = Ac[mrow * GST + kk + 4];
                unsigned a3 = Ac[(mrow + 8) * GST + kk + 4];
#pragma unroll
                for (int nf = 0; nf < 8; nf++)
                    mma_tf32(acc[mf][nf], a0, a1, a2, a3, b0[nf], b1[nf]);
            }
        }
        if (t + 1 < nk) STORE(cur ^ 1);
        __syncthreads();
    }

#pragma unroll
    for (int mf = 0; mf < 2; mf++) {
        int r0 = bm + wm + mf * 16 + fr;
        int ra = r0, rb = r0 + 8;
        if (fO) {
            int mb = r0 & ~(SEQ - 1);
            int ta = r0 & (SEQ - 1), tb = ta + 8;
            ta = (ta < blen) ? (blen - 1 - ta) : ta;
            tb = (tb < blen) ? (blen - 1 - tb) : tb;
            ra = mb + ta; rb = mb + tb;
        }
#pragma unroll
        for (int nf = 0; nf < 8; nf++) {
            int cc = bn + wn + nf * 8 + 2 * fc;
            if (cc < N) {
                float bz0 = bias ? bias[cc] : 0.f;
                float bz1 = bias ? bias[cc + 1] : 0.f;
                float2 v0 = make_float2(acc[mf][nf][0] + bz0, acc[mf][nf][1] + bz1);
                float2 v1 = make_float2(acc[mf][nf][2] + bz0, acc[mf][nf][3] + bz1);
                *(float2*)&C[(size_t)ra * ldc + cc] = v0;
                *(float2*)&C[(size_t)rb * ldc + cc] = v1;
            }
        }
    }
}

// ---------------- embedding gather ----------------
__global__ void gather_embed(const int* __restrict__ tok,
                             const float* __restrict__ emb,
                             float* __restrict__ x0)
{
    int x = blockIdx.x * 256 + threadIdx.x;
    int c = x & 511;
    int m = x >> 9;
    x0[x] = emb[(size_t)tok[m] * HDIM + c];
}

// ---------------- depthwise conv (k=4), 4 timesteps/thread, 2 dirs -------
__global__ void conv_kernel(const float* __restrict__ zx0, const float* __restrict__ zx1,
                            const float* __restrict__ wbase, const float* __restrict__ bbase,
                            float* __restrict__ xc0, float* __restrict__ xc1)
{
    const int d = blockIdx.y;
    const float* zx = d ? zx1 : zx0;
    float* xc = d ? xc1 : xc0;
    const float* w = wbase + d * CONVD * 4;
    const float* bias = bbase + d * CONVD;

    int x = blockIdx.x * 256 + threadIdx.x;
    int c = x % CONVD;
    int r = x / CONVD;
    int tq = r & (SEQ / 4 - 1);
    int b  = r / (SEQ / 4);
    int t0 = tq * 4;
    const float* base = zx + ((size_t)(b * SEQ + t0)) * DPROJ + DINNER + c;
    float w0 = w[c*4], w1 = w[c*4+1], w2 = w[c*4+2], w3 = w[c*4+3], bs = bias[c];
    float v[7];
#pragma unroll
    for (int j = 0; j < 7; j++) {
        int tau = t0 - 3 + j;
        v[j] = (tau >= 0) ? base[(long)(j - 3) * DPROJ] : 0.f;
    }
#pragma unroll
    for (int tt = 0; tt < 4; tt++) {
        float a = bs + w0 * v[tt] + w1 * v[tt+1] + w2 * v[tt+2] + w3 * v[tt+3];
        xc[((size_t)(b * SEQ + t0 + tt)) * CONVD + c] = a / (1.f + __expf(-a));
    }
}

// ---------------- dt = softplus(dt_raw + bias), 2 dirs ----------------
__global__ void dt_kernel(const float* __restrict__ zx0, const float* __restrict__ zx1,
                          const float* __restrict__ dtb,
                          float* __restrict__ dt0, float* __restrict__ dt1)
{
    const int d = blockIdx.y;
    const float* zx = d ? zx1 : zx0;
    float* dto = d ? dt1 : dt0;
    int x = blockIdx.x * 256 + threadIdx.x;
    int h = x & 15;
    int bl = x >> 4;
    float v = zx[(size_t)bl * DPROJ + (DINNER + CONVD) + h] + dtb[d * NHEADS + h];
    dto[x] = (v > 20.f) ? v : log1pf(__expf(v));
}

// ================= chunked SSM scan =================
__global__ __launch_bounds__(128) void chunk_state_kernel(
    const float* __restrict__ xc0, const float* __restrict__ xc1,
    const float* __restrict__ dtp0, const float* __restrict__ dtp1,
    const float* __restrict__ Alog,
    float* __restrict__ Sc, float* __restrict__ dec)
{
    const int c  = blockIdx.x;
    const int bh = blockIdx.y;
    const int d  = blockIdx.z;
    const int b = bh >> 4, h = bh & 15;
    const float* xc  = d ? xc1 : xc0;
    const float* dtp = d ? dtp1 : dtp0;
    const int tid = threadIdx.x;
    const int t0 = c * CH;

    __shared__ float dts[CH], cA[CH], ws[CH];
    __shared__ __align__(8) float XW[CH][66];
    __shared__ __align__(8) float Bsm[CH][66];

    if (tid < CH) {
        float dtv = dtp[(size_t)(b * SEQ + t0 + tid) * NHEADS + h];
        dts[tid] = dtv;
        cA[tid]  = __expf(Alog[d * NHEADS + h]) * dtv;
    }
    __syncthreads();
    if (tid < 32) {
        float v0 = cA[tid], v1 = cA[tid + 32];
#pragma unroll
        for (int o = 1; o < 32; o <<= 1) {
            float u0 = __shfl_up_sync(0xffffffffu, v0, o);
            float u1 = __shfl_up_sync(0xffffffffu, v1, o);
            if (tid >= o) { v0 += u0; v1 += u1; }
        }
        float tot = __shfl_sync(0xffffffffu, v0, 31);
        cA[tid] = v0;
        cA[tid + 32] = v1 + tot;
    }
    __syncthreads();
    const float cAend = cA[CH - 1];
    if (tid < CH) ws[tid] = __expf(cA[tid] - cAend) * dts[tid];
    if (tid == 0) dec[((size_t)d * 128 + bh) * NCH + c] = __expf(-cAend);
    __syncthreads();

    const size_t rbase = (size_t)(b * SEQ + t0) * CONVD;
#pragma unroll
    for (int k = 0; k < 32; k++) {
        int i = k * 128 + tid;
        int tt = i >> 6, pp = i & 63;
        XW [tt][pp] = xc[rbase + (size_t)tt * CONVD + h * HEADD + pp] * ws[tt];
        Bsm[tt][pp] = xc[rbase + (size_t)tt * CONVD + DINNER + pp];
    }
    __syncthreads();

    const int pg = (tid >> 3) * 4;
    const int sg = (tid & 7) * 8;
    u64 acc[4][4];
#pragma unroll
    for (int a_ = 0; a_ < 4; a_++)
#pragma unroll
        for (int b_ = 0; b_ < 4; b_++) acc[a_][b_] = 0ull;

    for (int tt = 0; tt < CH; tt++) {
        float2 f01 = unpack2(*(const u64*)&XW[tt][pg]);
        float2 f23 = unpack2(*(const u64*)&XW[tt][pg + 2]);
        u64 ap[4] = { pack2(f01.x, f01.x), pack2(f01.y, f01.y),
                      pack2(f23.x, f23.x), pack2(f23.y, f23.y) };
        u64 b0 = *(const u64*)&Bsm[tt][sg];
        u64 b1 = *(const u64*)&Bsm[tt][sg + 2];
        u64 b2 = *(const u64*)&Bsm[tt][sg + 4];
        u64 b3 = *(const u64*)&Bsm[tt][sg + 6];
#pragma unroll
        for (int pi = 0; pi < 4; pi++) {
            acc[pi][0] = fma2(b0, ap[pi], acc[pi][0]);
            acc[pi][1] = fma2(b1, ap[pi], acc[pi][1]);
            acc[pi][2] = fma2(b2, ap[pi], acc[pi][2]);
            acc[pi][3] = fma2(b3, ap[pi], acc[pi][3]);
        }
    }

    size_t ob = (((size_t)d * 128 + bh) * NCH + c) * 4096;
#pragma unroll
    for (int pi = 0; pi < 4; pi++)
#pragma unroll
        for (int j = 0; j < 4; j++)
            *(u64*)&Sc[ob + (size_t)(pg + pi) * 64 + sg + 2 * j] = acc[pi][j];
}

__global__ __launch_bounds__(256) void chunk_seq_kernel(
    const float* __restrict__ Sc, const float* __restrict__ dec,
    float* __restrict__ Sin)
{
    const int gid = blockIdx.x * 256 + threadIdx.x;
    const int bhd = gid >> 10;
    const int off = gid & 1023;
    float4 run = make_float4(0.f, 0.f, 0.f, 0.f);
    const float* dp = dec + bhd * NCH;
#pragma unroll 4
    for (int c = 0; c < NCH; c++) {
        size_t o = (((size_t)bhd * NCH + c) << 10) + off;
        *(float4*)&Sin[o * 4] = run;
        float4 s4 = *(const float4*)&Sc[o * 4];
        float dcv = dp[c];
        run.x = run.x * dcv + s4.x;
        run.y = run.y * dcv + s4.y;
        run.z = run.z * dcv + s4.z;
        run.w = run.w * dcv + s4.w;
    }
}

#define S3_SMEM (5*CH*66*4)
__global__ __launch_bounds__(128) void chunk_out_kernel(
    const float* __restrict__ xc0, const float* __restrict__ xc1,
    const float* __restrict__ zx0, const float* __restrict__ zx1,
    const float* __restrict__ dtp0, const float* __restrict__ dtp1,
    const float* __restrict__ Alog, const float* __restrict__ Dp,
    const float* __restrict__ Sin,
    float* __restrict__ y0, float* __restrict__ y1)
{
    const int c  = blockIdx.x;
    const int bh = blockIdx.y;
    const int d  = blockIdx.z;
    const int b = bh >> 4, h = bh & 15;
    const float* xc  = d ? xc1 : xc0;
    const float* zx  = d ? zx1 : zx0;
    const float* dtp = d ? dtp1 : dtp0;
    float* y = d ? y1 : y0;
    const int tid = threadIdx.x;
    const int t0 = c * CH;

    extern __shared__ __align__(8) float sm[];
    float* CsT  = sm;
    float* BsT  = sm + 1 * CH * 66;
    float* Xs   = sm + 2 * CH * 66;
    float* SinT = sm + 3 * CH * 66;
    float* WGT  = sm + 4 * CH * 66;
    __shared__ float dts[CH], cA[CH], rowdec[CH];

    const int tr0 = (tid >> 3) * 4;
    const int p0  = (tid & 7) * 8;

    float4 zr[4][2];
    const size_t zrow = (size_t)(b * SEQ + t0);
#pragma unroll
    for (int ti = 0; ti < 4; ti++) {
        const float* zp = zx + (zrow + tr0 + ti) * DPROJ + h * HEADD + p0;
        zr[ti][0] = *(const float4*)zp;
        zr[ti][1] = *(const float4*)(zp + 4);
    }

    if (tid < CH) {
        float dtv = dtp[(size_t)(b * SEQ + t0 + tid) * NHEADS + h];
        dts[tid] = dtv;
        cA[tid]  = __expf(Alog[d * NHEADS + h]) * dtv;
    }
    __syncthreads();
    if (tid < 32) {
        float v0 = cA[tid], v1 = cA[tid + 32];
#pragma unroll
        for (int o = 1; o < 32; o <<= 1) {
            float u0 = __shfl_up_sync(0xffffffffu, v0, o);
            float u1 = __shfl_up_sync(0xffffffffu, v1, o);
            if (tid >= o) { v0 += u0; v1 += u1; }
        }
        float tot = __shfl_sync(0xffffffffu, v0, 31);
        cA[tid] = v0;
        cA[tid + 32] = v1 + tot;
    }
    __syncthreads();
    if (tid < CH) rowdec[tid] = __expf(-cA[tid]);

    const size_t rbase = (size_t)(b * SEQ + t0) * CONVD;
    const size_t sinb = (((size_t)d * 128 + bh) * NCH + c) * 4096;
#pragma unroll
    for (int k = 0; k < 32; k++) {
        int i = k * 128 + tid;
        int tt = i >> 6, pp = i & 63;
        Xs  [tt * 66 + pp] = xc[rbase + (size_t)tt * CONVD + h * HEADD + pp];
        BsT [pp * 66 + tt] = xc[rbase + (size_t)tt * CONVD + DINNER + pp];
        CsT [pp * 66 + tt] = xc[rbase + (size_t)tt * CONVD + DINNER + DSTATE + pp];
        SinT[pp * 66 + tt] = Sin[sinb + (size_t)tt * 64 + pp];
    }
    __syncthreads();

    u64 acc[4][4];
#pragma unroll
    for (int a_ = 0; a_ < 4; a_++)
#pragma unroll
        for (int b_ = 0; b_ < 4; b_++) acc[a_][b_] = 0ull;

    for (int s = 0; s < CH; s++) {
        float2 f01 = unpack2(*(const u64*)&CsT[s * 66 + tr0]);
        float2 f23 = unpack2(*(const u64*)&CsT[s * 66 + tr0 + 2]);
        u64 ap[4] = { pack2(f01.x, f01.x), pack2(f01.y, f01.y),
                      pack2(f23.x, f23.x), pack2(f23.y, f23.y) };
        u64 b0 = *(const u64*)&BsT[s * 66 + p0];
        u64 b1 = *(const u64*)&BsT[s * 66 + p0 + 2];
        u64 b2 = *(const u64*)&BsT[s * 66 + p0 + 4];
        u64 b3 = *(const u64*)&BsT[s * 66 + p0 + 6];
#pragma unroll
        for (int pi = 0; pi < 4; pi++) {
            acc[pi][0] = fma2(b0, ap[pi], acc[pi][0]);
            acc[pi][1] = fma2(b1, ap[pi], acc[pi][1]);
            acc[pi][2] = fma2(b2, ap[pi], acc[pi][2]);
            acc[pi][3] = fma2(b3, ap[pi], acc[pi][3]);
        }
    }

#pragma unroll
    for (int ti = 0; ti < 4; ti++) {
        int t = tr0 + ti;
        float cat = cA[t];
#pragma unroll
        for (int j = 0; j < 4; j++) {
            float2 g = unpack2(acc[ti][j]);
            int ta0 = p0 + 2 * j, ta1 = ta0 + 1;
            float w0 = (ta0 <= t) ? __expf(cA[ta0] - cat) * dts[ta0] : 0.f;
            float w1 = (ta1 <= t) ? __expf(cA[ta1] - cat) * dts[ta1] : 0.f;
            WGT[ta0 * 66 + t] = g.x * w0;
            WGT[ta1 * 66 + t] = g.y * w1;
        }
    }
    __syncthreads();

#pragma unroll
    for (int a_ = 0; a_ < 4; a_++)
#pragma unroll
        for (int b_ = 0; b_ < 4; b_++) acc[a_][b_] = 0ull;

    for (int s = 0; s < CH; s++) {
        float2 f01 = unpack2(*(const u64*)&CsT[s * 66 + tr0]);
        float2 f23 = unpack2(*(const u64*)&CsT[s * 66 + tr0 + 2]);
        u64 ap[4] = { pack2(f01.x, f01.x), pack2(f01.y, f01.y),
                      pack2(f23.x, f23.x), pack2(f23.y, f23.y) };
        u64 b0 = *(const u64*)&SinT[s * 66 + p0];
        u64 b1 = *(const u64*)&SinT[s * 66 + p0 + 2];
        u64 b2 = *(const u64*)&SinT[s * 66 + p0 + 4];
        u64 b3 = *(const u64*)&SinT[s * 66 + p0 + 6];
#pragma unroll
        for (int pi = 0; pi < 4; pi++) {
            acc[pi][0] = fma2(b0, ap[pi], acc[pi][0]);
            acc[pi][1] = fma2(b1, ap[pi], acc[pi][1]);
            acc[pi][2] = fma2(b2, ap[pi], acc[pi][2]);
            acc[pi][3] = fma2(b3, ap[pi], acc[pi][3]);
        }
    }
#pragma unroll
    for (int ti = 0; ti < 4; ti++) {
        u64 rd2 = pack2(rowdec[tr0 + ti], rowdec[tr0 + ti]);
#pragma unroll
        for (int j = 0; j < 4; j++) acc[ti][j] = mul2(acc[ti][j], rd2);
    }

    for (int tt = 0; tt < CH; tt++) {
        float2 f01 = unpack2(*(const u64*)&WGT[tt * 66 + tr0]);
        float2 f23 = unpack2(*(const u64*)&WGT[tt * 66 + tr0 + 2]);
        u64 ap[4] = { pack2(f01.x, f01.x), pack2(f01.y, f01.y),
                      pack2(f23.x, f23.x), pack2(f23.y, f23.y) };
        u64 b0 = *(const u64*)&Xs[tt * 66 + p0];
        u64 b1 = *(const u64*)&Xs[tt * 66 + p0 + 2];
        u64 b2 = *(const u64*)&Xs[tt * 66 + p0 + 4];
        u64 b3 = *(const u64*)&Xs[tt * 66 + p0 + 6];
#pragma unroll
        for (int pi = 0; pi < 4; pi++) {
            acc[pi][0] = fma2(b0, ap[pi], acc[pi][0]);
            acc[pi][1] = fma2(b1, ap[pi], acc[pi][1]);
            acc[pi][2] = fma2(b2, ap[pi], acc[pi][2]);
            acc[pi][3] = fma2(b3, ap[pi], acc[pi][3]);
        }
    }

    const float Dv = Dp[d * NHEADS + h];
#pragma unroll
    for (int ti = 0; ti < 4; ti++) {
        int t = tr0 + ti;
        float out[8];
#pragma unroll
        for (int j = 0; j < 4; j++) {
            float2 a2 = unpack2(acc[ti][j]);
            out[2*j]   = a2.x + Dv * Xs[t * 66 + p0 + 2*j];
            out[2*j+1] = a2.y + Dv * Xs[t * 66 + p0 + 2*j + 1];
        }
        const float* zv = (const float*)&zr[ti][0];
#pragma unroll
        for (int e = 0; e < 8; e++) {
            float z = zv[e];
            out[e] *= z / (1.f + __expf(-z));
        }
        float* yp = y + (size_t)(b * SEQ + t0 + t) * DINNER + h * HEADD + p0;
        *(float4*)yp       = make_float4(out[0], out[1], out[2], out[3]);
        *(float4*)(yp + 4) = make_float4(out[4], out[5], out[6], out[7]);
    }
}

// ---------------- RMSNorm, both directions via blockIdx.y ----------------
__global__ __launch_bounds__(256) void rmsnorm_kernel(
    float* __restrict__ y0, float* __restrict__ y1,
    const float* __restrict__ wbase)
{
    const int dirn = blockIdx.y;
    float* p = (dirn ? y1 : y0) + (size_t)blockIdx.x * DINNER;
    const float* w = wbase + dirn * DINNER;
    int tid = threadIdx.x;
    float v[4];
    float ss = 0.f;
#pragma unroll
    for (int i = 0; i < 4; i++) { v[i] = p[tid + i * 256]; ss += v[i] * v[i]; }
#pragma unroll
    for (int o = 16; o; o >>= 1) ss += __shfl_xor_sync(0xffffffffu, ss, o);
    __shared__ float red[8];
    if ((tid & 31) == 0) red[tid >> 5] = ss;
    __syncthreads();
    float tot = 0.f;
#pragma unroll
    for (int i = 0; i < 8; i++) tot += red[i];
    float sc = rsqrtf(tot * (1.f / DINNER) + EPSLN);
#pragma unroll
    for (int i = 0; i < 4; i++)
        p[tid + i * 256] = v[i] * sc * w[tid + i * 256];
}

// ---------------- add + layernorm ----------------
__global__ __launch_bounds__(128) void addln_kernel(const float* __restrict__ out,
                                                    float* __restrict__ h,
                                                    const float* __restrict__ g,
                                                    const float* __restrict__ bta)
{
    int row = blockIdx.x;
    const float* po = out + (size_t)row * HDIM;
    float* ph = h + (size_t)row * HDIM;
    int tid = threadIdx.x;
    float v[4];
    float sum = 0.f;
#pragma unroll
    for (int i = 0; i < 4; i++) { v[i] = po[tid + i * 128] + ph[tid + i * 128]; sum += v[i]; }
#pragma unroll
    for (int o = 16; o; o >>= 1) sum += __shfl_xor_sync(0xffffffffu, sum, o);
    __shared__ float red[4];
    if ((tid & 31) == 0) red[tid >> 5] = sum;
    __syncthreads();
    float mean = (red[0] + red[1] + red[2] + red[3]) * (1.f / HDIM);
    float vs = 0.f;
#pragma unroll
    for (int i = 0; i < 4; i++) { float dd = v[i] - mean; vs += dd * dd; }
#pragma unroll
    for (int o = 16; o; o >>= 1) vs += __shfl_xor_sync(0xffffffffu, vs, o);
    __syncthreads();
    if ((tid & 31) == 0) red[tid >> 5] = vs;
    __syncthreads();
    float var = (red[0] + red[1] + red[2] + red[3]) * (1.f / HDIM);
    float sc = rsqrtf(var + EPSLN);
#pragma unroll
    for (int i = 0; i < 4; i++) {
        int c = tid + i * 128;
        ph[c] = (v[i] - mean) * sc * g[c] + bta[c];
    }
}

// ---------------- masked mean pool ----------------
__global__ __launch_bounds__(256) void pool_kernel(const float* __restrict__ enc,
                                                   const int* __restrict__ lens,
                                                   float* __restrict__ pooled)
{
    int b  = blockIdx.x >> 5;
    int c0 = (blockIdx.x & 31) * 32;
    int c  = threadIdx.x & 31;
    int ts = threadIdx.x >> 5;
    int len = lens[b];
    float s = 0.f;
    for (int t = ts; t < len; t += 8)
        s += enc[((size_t)(b * SEQ + t)) * (2 * HDIM) + c0 + c];
    __shared__ float red[8][32];
    red[ts][c] = s;
    __syncthreads();
    if (ts == 0) {
        float tot = 0.f;
#pragma unroll
        for (int i = 0; i < 8; i++) tot += red[i][c];
        pooled[b * (2 * HDIM) + c0 + c] = tot / (float)(len > 0 ? len : 1);
    }
}

// ---------------- adapter ----------------
__global__ __launch_bounds__(256) void adapter_kernel(const float* __restrict__ pooled,
                                                      const float* __restrict__ Wad,
                                                      const float* __restrict__ bad,
                                                      float* __restrict__ out)
{
    int w = blockIdx.x * 8 + (threadIdx.x >> 5);
    int lane = threadIdx.x & 31;
    int o = w & 511, b = w >> 9;
    const float* pr = pooled + (size_t)b * (2 * HDIM);
    const float* wr = Wad + (size_t)o * (2 * HDIM);
    float s = 0.f;
    for (int i = lane; i < 2 * HDIM; i += 32) s += pr[i] * wr[i];
#pragma unroll
    for (int off = 16; off; off >>= 1) s += __shfl_xor_sync(0xffffffffu, s, off);
    if (lane == 0) out[b * HDIM + o] = tanhf(s + bad[o]);
}

// ---------------- host ----------------
static float* symaddr(const void* s)
{
    void* p = nullptr;
    cudaGetSymbolAddress(&p, s);
    return (float*)p;
}

extern "C" void kernel_launch(void* const* d_in, const int* in_sizes, int n_in,
                              void* d_out, int out_size)
{
    const int*   tok    = (const int*)  d_in[0];
    const int*   lens   = (const int*)  d_in[1];
    const float* emb    = (const float*)d_in[2];
    const float* W_inp  = (const float*)d_in[3];
    const float* b_inp  = (const float*)d_in[4];
    const float* m_Win  = (const float*)d_in[5];
    const float* m_cw   = (const float*)d_in[6];
    const float* m_cb   = (const float*)d_in[7];
    const float* m_dtb  = (const float*)d_in[8];
    const float* m_Alog = (const float*)d_in[9];
    const float* m_D    = (const float*)d_in[10];
    const float* m_norm = (const float*)d_in[11];
    const float* m_Wout = (const float*)d_in[12];
    const float* blk_Wo = (const float*)d_in[13];
    const float* blk_bo = (const float*)d_in[14];
    const float* ln_g   = (const float*)d_in[15];
    const float* ln_b   = (const float*)d_in[16];
    const float* W_enc  = (const float*)d_in[17];
    const float* b_enc  = (const float*)d_in[18];
    const float* W_ad   = (const float*)d_in[19];
    const float* b_ad   = (const float*)d_in[20];
    float* outp = (float*)d_out;

    float* x0  = symaddr(g_x0);
    float* h   = symaddr(g_h);
    float* zx0 = symaddr(g_zx0);
    float* zx1 = symaddr(g_zx1);
    float* xc0 = symaddr(g_xc0);
    float* xc1 = symaddr(g_xc1);
    float* dt0 = symaddr(g_dt0);
    float* dt1 = symaddr(g_dt1);
    float* y0  = symaddr(g_y0);
    float* y1  = symaddr(g_y1);
    float* cb  = symaddr(g_cb);
    float* ot  = symaddr(g_ot);
    float* pl  = symaddr(g_pl);
    float* Sc  = symaddr(g_Sc);
    float* Sin = symaddr(g_Sin);
    float* dec = symaddr(g_dec);

    static int smem_set = 0;
    if (!smem_set) {
        cudaFuncSetAttribute(tf32gemm, cudaFuncAttributeMaxDynamicSharedMemorySize, GEMM_SMEM);
        cudaFuncSetAttribute(chunk_out_kernel, cudaFuncAttributeMaxDynamicSharedMemorySize, S3_SMEM);
        smem_set = 1;
    }

    const int TPB = 256;
    dim3 gEl(ML * HDIM / TPB);
    dim3 gConv((ML / 4) * CONVD / TPB, 2);
    dim3 gDt((ML * NHEADS) / TPB, 2);

    gather_embed<<<gEl, TPB>>>(tok, emb, x0);
    // embed projection (single)
    tf32gemm<<<dim3(4, ML / 128, 1), 256, GEMM_SMEM>>>(
        x0, nullptr, W_inp, nullptr, b_inp, h, nullptr,
        ML, HDIM, HDIM, HDIM, nullptr, 0, 0);

    for (int i = 0; i < 4; i++) {
        const float* Win0 = m_Win + (size_t)(i * 2 + 0) * DPROJ * HDIM;
        const float* Win1 = m_Win + (size_t)(i * 2 + 1) * DPROJ * HDIM;
        const float* Wo0  = m_Wout + (size_t)(i * 2 + 0) * HDIM * DINNER;
        const float* Wo1  = m_Wout + (size_t)(i * 2 + 1) * HDIM * DINNER;

        // in-projections, both directions; bwd reads h through the flip map
        tf32gemm<<<dim3((DPROJ + 127) / 128, ML / 128, 2), 256, GEMM_SMEM>>>(
            h, h, Win0, Win1, nullptr, zx0, zx1,
            ML, DPROJ, HDIM, DPROJ, lens, 1, 0);

        conv_kernel<<<gConv, TPB>>>(zx0, zx1,
                                    m_cw + (size_t)i * 2 * CONVD * 4,
                                    m_cb + (size_t)i * 2 * CONVD, xc0, xc1);
        dt_kernel<<<gDt, TPB>>>(zx0, zx1, m_dtb + i * 2 * NHEADS, dt0, dt1);

        chunk_state_kernel<<<dim3(NCH, 128, 2), 128>>>(
            xc0, xc1, dt0, dt1, m_Alog + i * 2 * NHEADS, Sc, dec);
        chunk_seq_kernel<<<1024, 256>>>(Sc, dec, Sin);
        chunk_out_kernel<<<dim3(NCH, 128, 2), 128, S3_SMEM>>>(
            xc0, xc1, zx0, zx1, dt0, dt1,
            m_Alog + i * 2 * NHEADS, m_D + i * 2 * NHEADS, Sin, y0, y1);

        rmsnorm_kernel<<<dim3(ML, 2), 256>>>(y0, y1, m_norm + (size_t)i * 2 * DINNER);

        // out-projections, both directions; fwd -> cb[:, :512],
        // bwd -> cb[:, 512:] with flipped output rows (fuses flipcat)
        tf32gemm<<<dim3(4, ML / 128, 2), 256, GEMM_SMEM>>>(
            y0, y1, Wo0, Wo1, nullptr, cb, cb + HDIM,
            ML, HDIM, DINNER, DINNER, lens, 0, 1);

        tf32gemm<<<dim3(4, ML / 128, 1), 256, GEMM_SMEM>>>(
            cb, nullptr, blk_Wo + (size_t)i * HDIM * DINNER, nullptr,
            blk_bo + i * HDIM, ot, nullptr,
            ML, HDIM, DINNER, HDIM, nullptr, 0, 0);
        addln_kernel<<<ML, 128>>>(ot, h, ln_g + i * HDIM, ln_b + i * HDIM);
    }

    tf32gemm<<<dim3(8, ML / 128, 1), 256, GEMM_SMEM>>>(
        h, nullptr, W_enc, nullptr, b_enc, outp, nullptr,
        ML, 2 * HDIM, HDIM, 2 * HDIM, nullptr, 0, 0);

    pool_kernel<<<BATCH * 32, 256>>>(outp, lens, pl);
    adapter_kernel<<<(BATCH * HDIM) / 8, 256>>>(pl, W_ad, b_ad,
                                                outp + (size_t)ML * 2 * HDIM);
}

// round 17
// speedup vs baseline: 1.2270x; 1.1751x over previous
#include <cuda_runtime.h>
#include <cuda_bf16.h>
#include <math.h>

// ---------------- problem constants ----------------
#define BATCH   8
#define SEQ     2048
#define HDIM    512
#define DPROJ   2192
#define DINNER  1024
#define DSTATE  64
#define NHEADS  16
#define HEADD   64
#define CONVD   1152
#define ML      (BATCH*SEQ)
#define EPSLN   1e-5f
#define CH      64
#define NCH     (SEQ/CH)

typedef unsigned long long u64;

// ---------------- device scratch ----------------
__device__ float g_x0 [ML*HDIM];
__device__ float g_h  [ML*HDIM];
__device__ float g_zx0[ML*DPROJ];
__device__ float g_zx1[ML*DPROJ];
__device__ float g_xc0[ML*CONVD];
__device__ float g_xc1[ML*CONVD];
__device__ float g_dt0[ML*NHEADS];
__device__ float g_dt1[ML*NHEADS];
__device__ float g_y0 [ML*DINNER];
__device__ float g_y1 [ML*DINNER];
__device__ float g_cb [ML*DINNER];
__device__ float g_ot [ML*HDIM];
__device__ float g_pl [BATCH*2*HDIM];
__device__ float g_Sc [2*128*NCH*4096];
__device__ float g_Sin[2*128*NCH*4096];
__device__ float g_dec[2*128*NCH];

// ---------------- helpers ----------------
__device__ __forceinline__ unsigned int f2tf32(float v)
{
    unsigned int u;
    asm("cvt.rna.tf32.f32 %0, %1;" : "=r"(u) : "f"(v));
    return u;
}

__device__ __forceinline__ void mma_tf32(float c[4],
                                         unsigned a0, unsigned a1, unsigned a2, unsigned a3,
                                         unsigned b0, unsigned b1)
{
    asm volatile(
        "mma.sync.aligned.m16n8k8.row.col.f32.tf32.tf32.f32 "
        "{%0,%1,%2,%3}, {%4,%5,%6,%7}, {%8,%9}, {%0,%1,%2,%3};"
        : "+f"(c[0]), "+f"(c[1]), "+f"(c[2]), "+f"(c[3])
        : "r"(a0), "r"(a1), "r"(a2), "r"(a3), "r"(b0), "r"(b1));
}

__device__ __forceinline__ u64 fma2(u64 a, u64 b, u64 c)
{
    u64 d; asm("fma.rn.f32x2 %0,%1,%2,%3;" : "=l"(d) : "l"(a), "l"(b), "l"(c)); return d;
}
__device__ __forceinline__ u64 pack2(float lo, float hi)
{
    u64 d; asm("mov.b64 %0,{%1,%2};" : "=l"(d) : "f"(lo), "f"(hi)); return d;
}
__device__ __forceinline__ float2 unpack2(u64 v)
{
    float2 r; asm("mov.b64 {%0,%1},%2;" : "=f"(r.x), "=f"(r.y) : "l"(v)); return r;
}

// ---------------- tf32 tensor-core GEMM, double-buffered, 1 sync/tile -----
#define GST 36
#define GSZ (128*GST)
#define GEMM_SMEM (4*GSZ*4)

__global__ __launch_bounds__(256, 2) void tf32gemm(
    const float* __restrict__ A0, const float* __restrict__ A1,
    const float* __restrict__ W0, const float* __restrict__ W1,
    const float* __restrict__ bias,
    float* __restrict__ C0, float* __restrict__ C1,
    int M, int N, int K, int ldc,
    const int* __restrict__ lens, int flipA1, int flipOut1)
{
    extern __shared__ __align__(16) unsigned int dsm[];

    const int z = blockIdx.z;
    const float* A = z ? A1 : A0;
    const float* W = z ? W1 : W0;
    float* C = z ? C1 : C0;

    const int tid  = threadIdx.x;
    const int lane = tid & 31;
    const int wid  = tid >> 5;
    const int wm   = (wid & 3) * 32;
    const int wn   = (wid >> 2) * 64;
    const int bm   = blockIdx.y * 128;
    const int bn   = blockIdx.x * 128;

    const int cm0 = tid >> 3;
    const int ckq = tid & 7;

    const int fr = lane >> 2;
    const int fc = lane & 3;

    const int blen = lens ? lens[bm >> 11] : 0;
    const bool fA  = (z && flipA1);
    const bool fO  = (z && flipOut1);

    float acc[2][8][4];
#pragma unroll
    for (int i = 0; i < 2; i++)
#pragma unroll
        for (int j = 0; j < 8; j++)
#pragma unroll
            for (int r = 0; r < 4; r++) acc[i][j][r] = 0.f;

    const int nk = K >> 5;
    float4 ar[4], wr[4];
    bool wvalid[4];
    const float* Aq[4];
#pragma unroll
    for (int q = 0; q < 4; q++) {
        wvalid[q] = (bn + cm0 + 32 * q) < N;
        int m = bm + cm0 + 32 * q;
        if (fA) {
            int t = m & (SEQ - 1);
            int mb = m & ~(SEQ - 1);
            t = (t < blen) ? (blen - 1 - t) : t;
            m = mb + t;
        }
        Aq[q] = A + (size_t)m * K + ckq * 4;
    }
    const float* Wbase = W + (size_t)(bn + cm0) * K + ckq * 4;

    auto LOAD = [&](int t) {
#pragma unroll
        for (int q = 0; q < 4; q++) {
            ar[q] = *(const float4*)(Aq[q] + t * 32);
            wr[q] = wvalid[q] ? *(const float4*)(Wbase + (size_t)(32 * q) * K + t * 32)
                              : make_float4(0.f, 0.f, 0.f, 0.f);
        }
    };
    auto STORE = [&](int buf) {
        unsigned int* Asb = dsm + buf * 2 * GSZ;
        unsigned int* Wsb = Asb + GSZ;
#pragma unroll
        for (int q = 0; q < 4; q++) {
            uint4 av = make_uint4(f2tf32(ar[q].x), f2tf32(ar[q].y), f2tf32(ar[q].z), f2tf32(ar[q].w));
            uint4 wv = make_uint4(f2tf32(wr[q].x), f2tf32(wr[q].y), f2tf32(wr[q].z), f2tf32(wr[q].w));
            *(uint4*)&Asb[(cm0 + 32 * q) * GST + ckq * 4] = av;
            *(uint4*)&Wsb[(cm0 + 32 * q) * GST + ckq * 4] = wv;
        }
    };

    LOAD(0);
    STORE(0);
    __syncthreads();

    for (int t = 0; t < nk; t++) {
        const int cur = t & 1;
        if (t + 1 < nk) LOAD(t + 1);

        const unsigned int* Ac = dsm + cur * 2 * GSZ;
        const unsigned int* Wc = Ac + GSZ;
#pragma unroll
        for (int ks = 0; ks < 4; ks++) {
            const int kk = ks * 8 + fc;
            unsigned b0[8], b1[8];
#pragma unroll
            for (int nf = 0; nf < 8; nf++) {
                int nrow = wn + nf * 8 + fr;
                b0[nf] = Wc[nrow * GST + kk];
                b1[nf] = Wc[nrow * GST + kk + 4];
            }
#pragma unroll
            for (int mf = 0; mf < 2; mf++) {
                int mrow = wm + mf * 16 + fr;
                unsigned a0 = Ac[mrow * GST + kk];
                unsigned a1 = Ac[(mrow + 8) * GST + kk];
                unsigned a2 = Ac[mrow * GST + kk + 4];
                unsigned a3 = Ac[(mrow + 8) * GST + kk + 4];
#pragma unroll
                for (int nf = 0; nf < 8; nf++)
                    mma_tf32(acc[mf][nf], a0, a1, a2, a3, b0[nf], b1[nf]);
            }
        }
        if (t + 1 < nk) STORE(cur ^ 1);
        __syncthreads();
    }

#pragma unroll
    for (int mf = 0; mf < 2; mf++) {
        int r0 = bm + wm + mf * 16 + fr;
        int ra = r0, rb = r0 + 8;
        if (fO) {
            int mb = r0 & ~(SEQ - 1);
            int ta = r0 & (SEQ - 1), tb = ta + 8;
            ta = (ta < blen) ? (blen - 1 - ta) : ta;
            tb = (tb < blen) ? (blen - 1 - tb) : tb;
            ra = mb + ta; rb = mb + tb;
        }
#pragma unroll
        for (int nf = 0; nf < 8; nf++) {
            int cc = bn + wn + nf * 8 + 2 * fc;
            if (cc < N) {
                float bz0 = bias ? bias[cc] : 0.f;
                float bz1 = bias ? bias[cc + 1] : 0.f;
                float2 v0 = make_float2(acc[mf][nf][0] + bz0, acc[mf][nf][1] + bz1);
                float2 v1 = make_float2(acc[mf][nf][2] + bz0, acc[mf][nf][3] + bz1);
                *(float2*)&C[(size_t)ra * ldc + cc] = v0;
                *(float2*)&C[(size_t)rb * ldc + cc] = v1;
            }
        }
    }
}

// ---------------- embedding gather ----------------
__global__ void gather_embed(const int* __restrict__ tok,
                             const float* __restrict__ emb,
                             float* __restrict__ x0)
{
    int x = blockIdx.x * 256 + threadIdx.x;
    int c = x & 511;
    int m = x >> 9;
    x0[x] = emb[(size_t)tok[m] * HDIM + c];
}

// ---------------- depthwise conv (k=4), 4 timesteps/thread, 2 dirs -------
__global__ void conv_kernel(const float* __restrict__ zx0, const float* __restrict__ zx1,
                            const float* __restrict__ wbase, const float* __restrict__ bbase,
                            float* __restrict__ xc0, float* __restrict__ xc1)
{
    const int d = blockIdx.y;
    const float* zx = d ? zx1 : zx0;
    float* xc = d ? xc1 : xc0;
    const float* w = wbase + d * CONVD * 4;
    const float* bias = bbase + d * CONVD;

    int x = blockIdx.x * 256 + threadIdx.x;
    int c = x % CONVD;
    int r = x / CONVD;
    int tq = r & (SEQ / 4 - 1);
    int b  = r / (SEQ / 4);
    int t0 = tq * 4;
    const float* base = zx + ((size_t)(b * SEQ + t0)) * DPROJ + DINNER + c;
    float w0 = w[c*4], w1 = w[c*4+1], w2 = w[c*4+2], w3 = w[c*4+3], bs = bias[c];
    float v[7];
#pragma unroll
    for (int j = 0; j < 7; j++) {
        int tau = t0 - 3 + j;
        v[j] = (tau >= 0) ? base[(long)(j - 3) * DPROJ] : 0.f;
    }
#pragma unroll
    for (int tt = 0; tt < 4; tt++) {
        float a = bs + w0 * v[tt] + w1 * v[tt+1] + w2 * v[tt+2] + w3 * v[tt+3];
        xc[((size_t)(b * SEQ + t0 + tt)) * CONVD + c] = a / (1.f + __expf(-a));
    }
}

// ---------------- dt = softplus(dt_raw + bias), 2 dirs ----------------
__global__ void dt_kernel(const float* __restrict__ zx0, const float* __restrict__ zx1,
                          const float* __restrict__ dtb,
                          float* __restrict__ dt0, float* __restrict__ dt1)
{
    const int d = blockIdx.y;
    const float* zx = d ? zx1 : zx0;
    float* dto = d ? dt1 : dt0;
    int x = blockIdx.x * 256 + threadIdx.x;
    int h = x & 15;
    int bl = x >> 4;
    float v = zx[(size_t)bl * DPROJ + (DINNER + CONVD) + h] + dtb[d * NHEADS + h];
    dto[x] = (v > 20.f) ? v : log1pf(__expf(v));
}

// ================= chunked SSM scan =================
// S1: per-chunk state contribution S_c[p][s] and chunk decay (fp32 exact).
__global__ __launch_bounds__(128) void chunk_state_kernel(
    const float* __restrict__ xc0, const float* __restrict__ xc1,
    const float* __restrict__ dtp0, const float* __restrict__ dtp1,
    const float* __restrict__ Alog,
    float* __restrict__ Sc, float* __restrict__ dec)
{
    const int c  = blockIdx.x;
    const int bh = blockIdx.y;
    const int d  = blockIdx.z;
    const int b = bh >> 4, h = bh & 15;
    const float* xc  = d ? xc1 : xc0;
    const float* dtp = d ? dtp1 : dtp0;
    const int tid = threadIdx.x;
    const int t0 = c * CH;

    __shared__ float dts[CH], cA[CH], ws[CH];
    __shared__ __align__(8) float XW[CH][66];
    __shared__ __align__(8) float Bsm[CH][66];

    if (tid < CH) {
        float dtv = dtp[(size_t)(b * SEQ + t0 + tid) * NHEADS + h];
        dts[tid] = dtv;
        cA[tid]  = __expf(Alog[d * NHEADS + h]) * dtv;
    }
    __syncthreads();
    if (tid < 32) {
        float v0 = cA[tid], v1 = cA[tid + 32];
#pragma unroll
        for (int o = 1; o < 32; o <<= 1) {
            float u0 = __shfl_up_sync(0xffffffffu, v0, o);
            float u1 = __shfl_up_sync(0xffffffffu, v1, o);
            if (tid >= o) { v0 += u0; v1 += u1; }
        }
        float tot = __shfl_sync(0xffffffffu, v0, 31);
        cA[tid] = v0;
        cA[tid + 32] = v1 + tot;
    }
    __syncthreads();
    const float cAend = cA[CH - 1];
    if (tid < CH) ws[tid] = __expf(cA[tid] - cAend) * dts[tid];
    if (tid == 0) dec[((size_t)d * 128 + bh) * NCH + c] = __expf(-cAend);
    __syncthreads();

    const size_t rbase = (size_t)(b * SEQ + t0) * CONVD;
#pragma unroll
    for (int k = 0; k < 32; k++) {
        int i = k * 128 + tid;
        int tt = i >> 6, pp = i & 63;
        XW [tt][pp] = xc[rbase + (size_t)tt * CONVD + h * HEADD + pp] * ws[tt];
        Bsm[tt][pp] = xc[rbase + (size_t)tt * CONVD + DINNER + pp];
    }
    __syncthreads();

    const int pg = (tid >> 3) * 4;
    const int sg = (tid & 7) * 8;
    u64 acc[4][4];
#pragma unroll
    for (int a_ = 0; a_ < 4; a_++)
#pragma unroll
        for (int b_ = 0; b_ < 4; b_++) acc[a_][b_] = 0ull;

    for (int tt = 0; tt < CH; tt++) {
        float2 f01 = unpack2(*(const u64*)&XW[tt][pg]);
        float2 f23 = unpack2(*(const u64*)&XW[tt][pg + 2]);
        u64 ap[4] = { pack2(f01.x, f01.x), pack2(f01.y, f01.y),
                      pack2(f23.x, f23.x), pack2(f23.y, f23.y) };
        u64 b0 = *(const u64*)&Bsm[tt][sg];
        u64 b1 = *(const u64*)&Bsm[tt][sg + 2];
        u64 b2 = *(const u64*)&Bsm[tt][sg + 4];
        u64 b3 = *(const u64*)&Bsm[tt][sg + 6];
#pragma unroll
        for (int pi = 0; pi < 4; pi++) {
            acc[pi][0] = fma2(b0, ap[pi], acc[pi][0]);
            acc[pi][1] = fma2(b1, ap[pi], acc[pi][1]);
            acc[pi][2] = fma2(b2, ap[pi], acc[pi][2]);
            acc[pi][3] = fma2(b3, ap[pi], acc[pi][3]);
        }
    }

    size_t ob = (((size_t)d * 128 + bh) * NCH + c) * 4096;
#pragma unroll
    for (int pi = 0; pi < 4; pi++)
#pragma unroll
        for (int j = 0; j < 4; j++)
            *(u64*)&Sc[ob + (size_t)(pg + pi) * 64 + sg + 2 * j] = acc[pi][j];
}

// S2: sequential over 32 chunks; one float4 column per thread.
__global__ __launch_bounds__(256) void chunk_seq_kernel(
    const float* __restrict__ Sc, const float* __restrict__ dec,
    float* __restrict__ Sin)
{
    const int gid = blockIdx.x * 256 + threadIdx.x;
    const int bhd = gid >> 10;
    const int off = gid & 1023;
    float4 run = make_float4(0.f, 0.f, 0.f, 0.f);
    const float* dp = dec + bhd * NCH;
#pragma unroll 4
    for (int c = 0; c < NCH; c++) {
        size_t o = (((size_t)bhd * NCH + c) << 10) + off;
        *(float4*)&Sin[o * 4] = run;
        float4 s4 = *(const float4*)&Sc[o * 4];
        float dcv = dp[c];
        run.x = run.x * dcv + s4.x;
        run.y = run.y * dcv + s4.y;
        run.z = run.z * dcv + s4.z;
        run.w = run.w * dcv + s4.w;
    }
}

// S3 (tensor-core): G=C·B^T, mask, Y = rowdec.*(C·Sin^T) + WG·X + D*x, gated.
// Mask exps computed as bounded differences exp(cA[tau]-cA[t]) (tau<=t) only.
#define OST 68
#define S3_SMEM (5*CH*OST*4)
__global__ __launch_bounds__(128, 2) void chunk_out_kernel(
    const float* __restrict__ xc0, const float* __restrict__ xc1,
    const float* __restrict__ zx0, const float* __restrict__ zx1,
    const float* __restrict__ dtp0, const float* __restrict__ dtp1,
    const float* __restrict__ Alog, const float* __restrict__ Dp,
    const float* __restrict__ Sin,
    float* __restrict__ y0, float* __restrict__ y1)
{
    const int c  = blockIdx.x;
    const int bh = blockIdx.y;
    const int d  = blockIdx.z;
    const int b = bh >> 4, h = bh & 15;
    const float* xc  = d ? xc1 : xc0;
    const float* zx  = d ? zx1 : zx0;
    const float* dtp = d ? dtp1 : dtp0;
    float* y = d ? y1 : y0;
    const int tid = threadIdx.x;
    const int lane = tid & 31;
    const int wm = (tid >> 5) * 16;
    const int g  = lane >> 2;
    const int tg = lane & 3;
    const int t0 = c * CH;

    extern __shared__ __align__(16) unsigned int usm[];
    unsigned int* Cs = usm;                // [t][s]
    unsigned int* Bt = usm + 1 * CH * OST; // [tau][s]
    unsigned int* Sp = usm + 2 * CH * OST; // [p][s]
    unsigned int* Xp = usm + 3 * CH * OST; // [p][tau]
    unsigned int* WG = usm + 4 * CH * OST; // [t][tau]
    __shared__ float dts[CH], cA[CH], rowdec[CH];

    if (tid < CH) {
        float dtv = dtp[(size_t)(b * SEQ + t0 + tid) * NHEADS + h];
        dts[tid] = dtv;
        cA[tid]  = __expf(Alog[d * NHEADS + h]) * dtv;
    }
    __syncthreads();
    if (tid < 32) {
        float v0 = cA[tid], v1 = cA[tid + 32];
#pragma unroll
        for (int o = 1; o < 32; o <<= 1) {
            float u0 = __shfl_up_sync(0xffffffffu, v0, o);
            float u1 = __shfl_up_sync(0xffffffffu, v1, o);
            if (tid >= o) { v0 += u0; v1 += u1; }
        }
        float tot = __shfl_sync(0xffffffffu, v0, 31);
        cA[tid] = v0;
        cA[tid + 32] = v1 + tot;
    }
    __syncthreads();
    if (tid < CH) rowdec[tid] = __expf(-cA[tid]);

    const size_t rbase = (size_t)(b * SEQ + t0) * CONVD;
    const size_t sinb = (((size_t)d * 128 + bh) * NCH + c) * 4096;
#pragma unroll
    for (int k = 0; k < 32; k++) {
        int i = k * 128 + tid;
        int r = i >> 6, cl = i & 63;
        Cs[r * OST + cl]  = f2tf32(xc[rbase + (size_t)r * CONVD + DINNER + DSTATE + cl]);
        Bt[r * OST + cl]  = f2tf32(xc[rbase + (size_t)r * CONVD + DINNER + cl]);
        Sp[r * OST + cl]  = f2tf32(Sin[sinb + (size_t)r * 64 + cl]);
        Xp[cl * OST + r]  = f2tf32(xc[rbase + (size_t)r * CONVD + h * HEADD + cl]);
    }
    __syncthreads();

    const int t1 = wm + g, t2 = wm + g + 8;

    // G = C @ B^T
    float gacc[8][4];
#pragma unroll
    for (int nf = 0; nf < 8; nf++)
#pragma unroll
        for (int r = 0; r < 4; r++) gacc[nf][r] = 0.f;
#pragma unroll
    for (int ks = 0; ks < 8; ks++) {
        int kk = ks * 8 + tg;
        unsigned a0 = Cs[t1 * OST + kk],     a1 = Cs[t2 * OST + kk];
        unsigned a2 = Cs[t1 * OST + kk + 4], a3 = Cs[t2 * OST + kk + 4];
#pragma unroll
        for (int nf = 0; nf < 8; nf++) {
            int nr = nf * 8 + g;
            mma_tf32(gacc[nf], a0, a1, a2, a3,
                     Bt[nr * OST + kk], Bt[nr * OST + kk + 4]);
        }
    }

    // mask by causal decay*dt (bounded difference exps), write WG[t][tau]
    {
        float ca1 = cA[t1], ca2 = cA[t2];
#pragma unroll
        for (int nf = 0; nf < 8; nf++) {
            int ta0 = nf * 8 + 2 * tg, ta1 = ta0 + 1;
            float w00 = (ta0 <= t1) ? __expf(cA[ta0] - ca1) * dts[ta0] : 0.f;
            float w01 = (ta1 <= t1) ? __expf(cA[ta1] - ca1) * dts[ta1] : 0.f;
            float w10 = (ta0 <= t2) ? __expf(cA[ta0] - ca2) * dts[ta0] : 0.f;
            float w11 = (ta1 <= t2) ? __expf(cA[ta1] - ca2) * dts[ta1] : 0.f;
            WG[t1 * OST + ta0] = f2tf32(gacc[nf][0] * w00);
            WG[t1 * OST + ta1] = f2tf32(gacc[nf][1] * w01);
            WG[t2 * OST + ta0] = f2tf32(gacc[nf][2] * w10);
            WG[t2 * OST + ta1] = f2tf32(gacc[nf][3] * w11);
        }
    }

    // Y1 = C @ Sin^T
    float yacc[8][4];
#pragma unroll
    for (int nf = 0; nf < 8; nf++)
#pragma unroll
        for (int r = 0; r < 4; r++) yacc[nf][r] = 0.f;
#pragma unroll
    for (int ks = 0; ks < 8; ks++) {
        int kk = ks * 8 + tg;
        unsigned a0 = Cs[t1 * OST + kk],     a1 = Cs[t2 * OST + kk];
        unsigned a2 = Cs[t1 * OST + kk + 4], a3 = Cs[t2 * OST + kk + 4];
#pragma unroll
        for (int nf = 0; nf < 8; nf++) {
            int nr = nf * 8 + g;
            mma_tf32(yacc[nf], a0, a1, a2, a3,
                     Sp[nr * OST + kk], Sp[nr * OST + kk + 4]);
        }
    }
    {
        float r1 = rowdec[t1], r2 = rowdec[t2];
#pragma unroll
        for (int nf = 0; nf < 8; nf++) {
            yacc[nf][0] *= r1; yacc[nf][1] *= r1;
            yacc[nf][2] *= r2; yacc[nf][3] *= r2;
        }
    }
    __syncthreads();   // WG visible

    // Y += WG @ X
#pragma unroll
    for (int ks = 0; ks < 8; ks++) {
        int kk = ks * 8 + tg;
        unsigned a0 = WG[t1 * OST + kk],     a1 = WG[t2 * OST + kk];
        unsigned a2 = WG[t1 * OST + kk + 4], a3 = WG[t2 * OST + kk + 4];
#pragma unroll
        for (int nf = 0; nf < 8; nf++) {
            int nr = nf * 8 + g;
            mma_tf32(yacc[nf], a0, a1, a2, a3,
                     Xp[nr * OST + kk], Xp[nr * OST + kk + 4]);
        }
    }

    // epilogue: + D*x (fp32), silu(z) gate, store
    const float Dv = Dp[d * NHEADS + h];
    const size_t gr1 = (size_t)(b * SEQ + t0 + t1);
    const size_t gr2 = (size_t)(b * SEQ + t0 + t2);
#pragma unroll
    for (int nf = 0; nf < 8; nf++) {
        int p = nf * 8 + 2 * tg;
        float2 x1 = *(const float2*)&xc[gr1 * CONVD + h * HEADD + p];
        float2 z1 = *(const float2*)&zx[gr1 * DPROJ + h * HEADD + p];
        float2 x2 = *(const float2*)&xc[gr2 * CONVD + h * HEADD + p];
        float2 z2 = *(const float2*)&zx[gr2 * DPROJ + h * HEADD + p];
        float o0 = yacc[nf][0] + Dv * x1.x;
        float o1 = yacc[nf][1] + Dv * x1.y;
        float o2 = yacc[nf][2] + Dv * x2.x;
        float o3 = yacc[nf][3] + Dv * x2.y;
        o0 *= z1.x / (1.f + __expf(-z1.x));
        o1 *= z1.y / (1.f + __expf(-z1.y));
        o2 *= z2.x / (1.f + __expf(-z2.x));
        o3 *= z2.y / (1.f + __expf(-z2.y));
        *(float2*)&y[gr1 * DINNER + h * HEADD + p] = make_float2(o0, o1);
        *(float2*)&y[gr2 * DINNER + h * HEADD + p] = make_float2(o2, o3);
    }
}

// ---------------- RMSNorm, both directions via blockIdx.y ----------------
__global__ __launch_bounds__(256) void rmsnorm_kernel(
    float* __restrict__ y0, float* __restrict__ y1,
    const float* __restrict__ wbase)
{
    const int dirn = blockIdx.y;
    float* p = (dirn ? y1 : y0) + (size_t)blockIdx.x * DINNER;
    const float* w = wbase + dirn * DINNER;
    int tid = threadIdx.x;
    float v[4];
    float ss = 0.f;
#pragma unroll
    for (int i = 0; i < 4; i++) { v[i] = p[tid + i * 256]; ss += v[i] * v[i]; }
#pragma unroll
    for (int o = 16; o; o >>= 1) ss += __shfl_xor_sync(0xffffffffu, ss, o);
    __shared__ float red[8];
    if ((tid & 31) == 0) red[tid >> 5] = ss;
    __syncthreads();
    float tot = 0.f;
#pragma unroll
    for (int i = 0; i < 8; i++) tot += red[i];
    float sc = rsqrtf(tot * (1.f / DINNER) + EPSLN);
#pragma unroll
    for (int i = 0; i < 4; i++)
        p[tid + i * 256] = v[i] * sc * w[tid + i * 256];
}

// ---------------- add + layernorm ----------------
__global__ __launch_bounds__(128) void addln_kernel(const float* __restrict__ out,
                                                    float* __restrict__ h,
                                                    const float* __restrict__ g,
                                                    const float* __restrict__ bta)
{
    int row = blockIdx.x;
    const float* po = out + (size_t)row * HDIM;
    float* ph = h + (size_t)row * HDIM;
    int tid = threadIdx.x;
    float v[4];
    float sum = 0.f;
#pragma unroll
    for (int i = 0; i < 4; i++) { v[i] = po[tid + i * 128] + ph[tid + i * 128]; sum += v[i]; }
#pragma unroll
    for (int o = 16; o; o >>= 1) sum += __shfl_xor_sync(0xffffffffu, sum, o);
    __shared__ float red[4];
    if ((tid & 31) == 0) red[tid >> 5] = sum;
    __syncthreads();
    float mean = (red[0] + red[1] + red[2] + red[3]) * (1.f / HDIM);
    float vs = 0.f;
#pragma unroll
    for (int i = 0; i < 4; i++) { float dd = v[i] - mean; vs += dd * dd; }
#pragma unroll
    for (int o = 16; o; o >>= 1) vs += __shfl_xor_sync(0xffffffffu, vs, o);
    __syncthreads();
    if ((tid & 31) == 0) red[tid >> 5] = vs;
    __syncthreads();
    float var = (red[0] + red[1] + red[2] + red[3]) * (1.f / HDIM);
    float sc = rsqrtf(var + EPSLN);
#pragma unroll
    for (int i = 0; i < 4; i++) {
        int c = tid + i * 128;
        ph[c] = (v[i] - mean) * sc * g[c] + bta[c];
    }
}

// ---------------- masked mean pool ----------------
__global__ __launch_bounds__(256) void pool_kernel(const float* __restrict__ enc,
                                                   const int* __restrict__ lens,
                                                   float* __restrict__ pooled)
{
    int b  = blockIdx.x >> 5;
    int c0 = (blockIdx.x & 31) * 32;
    int c  = threadIdx.x & 31;
    int ts = threadIdx.x >> 5;
    int len = lens[b];
    float s = 0.f;
    for (int t = ts; t < len; t += 8)
        s += enc[((size_t)(b * SEQ + t)) * (2 * HDIM) + c0 + c];
    __shared__ float red[8][32];
    red[ts][c] = s;
    __syncthreads();
    if (ts == 0) {
        float tot = 0.f;
#pragma unroll
        for (int i = 0; i < 8; i++) tot += red[i][c];
        pooled[b * (2 * HDIM) + c0 + c] = tot / (float)(len > 0 ? len : 1);
    }
}

// ---------------- adapter ----------------
__global__ __launch_bounds__(256) void adapter_kernel(const float* __restrict__ pooled,
                                                      const float* __restrict__ Wad,
                                                      const float* __restrict__ bad,
                                                      float* __restrict__ out)
{
    int w = blockIdx.x * 8 + (threadIdx.x >> 5);
    int lane = threadIdx.x & 31;
    int o = w & 511, b = w >> 9;
    const float* pr = pooled + (size_t)b * (2 * HDIM);
    const float* wr = Wad + (size_t)o * (2 * HDIM);
    float s = 0.f;
    for (int i = lane; i < 2 * HDIM; i += 32) s += pr[i] * wr[i];
#pragma unroll
    for (int off = 16; off; off >>= 1) s += __shfl_xor_sync(0xffffffffu, s, off);
    if (lane == 0) out[b * HDIM + o] = tanhf(s + bad[o]);
}

// ---------------- host ----------------
static float* symaddr(const void* s)
{
    void* p = nullptr;
    cudaGetSymbolAddress(&p, s);
    return (float*)p;
}

extern "C" void kernel_launch(void* const* d_in, const int* in_sizes, int n_in,
                              void* d_out, int out_size)
{
    const int*   tok    = (const int*)  d_in[0];
    const int*   lens   = (const int*)  d_in[1];
    const float* emb    = (const float*)d_in[2];
    const float* W_inp  = (const float*)d_in[3];
    const float* b_inp  = (const float*)d_in[4];
    const float* m_Win  = (const float*)d_in[5];
    const float* m_cw   = (const float*)d_in[6];
    const float* m_cb   = (const float*)d_in[7];
    const float* m_dtb  = (const float*)d_in[8];
    const float* m_Alog = (const float*)d_in[9];
    const float* m_D    = (const float*)d_in[10];
    const float* m_norm = (const float*)d_in[11];
    const float* m_Wout = (const float*)d_in[12];
    const float* blk_Wo = (const float*)d_in[13];
    const float* blk_bo = (const float*)d_in[14];
    const float* ln_g   = (const float*)d_in[15];
    const float* ln_b   = (const float*)d_in[16];
    const float* W_enc  = (const float*)d_in[17];
    const float* b_enc  = (const float*)d_in[18];
    const float* W_ad   = (const float*)d_in[19];
    const float* b_ad   = (const float*)d_in[20];
    float* outp = (float*)d_out;

    float* x0  = symaddr(g_x0);
    float* h   = symaddr(g_h);
    float* zx0 = symaddr(g_zx0);
    float* zx1 = symaddr(g_zx1);
    float* xc0 = symaddr(g_xc0);
    float* xc1 = symaddr(g_xc1);
    float* dt0 = symaddr(g_dt0);
    float* dt1 = symaddr(g_dt1);
    float* y0  = symaddr(g_y0);
    float* y1  = symaddr(g_y1);
    float* cb  = symaddr(g_cb);
    float* ot  = symaddr(g_ot);
    float* pl  = symaddr(g_pl);
    float* Sc  = symaddr(g_Sc);
    float* Sin = symaddr(g_Sin);
    float* dec = symaddr(g_dec);

    static int smem_set = 0;
    if (!smem_set) {
        cudaFuncSetAttribute(tf32gemm, cudaFuncAttributeMaxDynamicSharedMemorySize, GEMM_SMEM);
        cudaFuncSetAttribute(chunk_out_kernel, cudaFuncAttributeMaxDynamicSharedMemorySize, S3_SMEM);
        smem_set = 1;
    }

    const int TPB = 256;
    dim3 gEl(ML * HDIM / TPB);
    dim3 gConv((ML / 4) * CONVD / TPB, 2);
    dim3 gDt((ML * NHEADS) / TPB, 2);

    gather_embed<<<gEl, TPB>>>(tok, emb, x0);
    tf32gemm<<<dim3(4, ML / 128, 1), 256, GEMM_SMEM>>>(
        x0, nullptr, W_inp, nullptr, b_inp, h, nullptr,
        ML, HDIM, HDIM, HDIM, nullptr, 0, 0);

    for (int i = 0; i < 4; i++) {
        const float* Win0 = m_Win + (size_t)(i * 2 + 0) * DPROJ * HDIM;
        const float* Win1 = m_Win + (size_t)(i * 2 + 1) * DPROJ * HDIM;
        const float* Wo0  = m_Wout + (size_t)(i * 2 + 0) * HDIM * DINNER;
        const float* Wo1  = m_Wout + (size_t)(i * 2 + 1) * HDIM * DINNER;

        tf32gemm<<<dim3((DPROJ + 127) / 128, ML / 128, 2), 256, GEMM_SMEM>>>(
            h, h, Win0, Win1, nullptr, zx0, zx1,
            ML, DPROJ, HDIM, DPROJ, lens, 1, 0);

        conv_kernel<<<gConv, TPB>>>(zx0, zx1,
                                    m_cw + (size_t)i * 2 * CONVD * 4,
                                    m_cb + (size_t)i * 2 * CONVD, xc0, xc1);
        dt_kernel<<<gDt, TPB>>>(zx0, zx1, m_dtb + i * 2 * NHEADS, dt0, dt1);

        chunk_state_kernel<<<dim3(NCH, 128, 2), 128>>>(
            xc0, xc1, dt0, dt1, m_Alog + i * 2 * NHEADS, Sc, dec);
        chunk_seq_kernel<<<1024, 256>>>(Sc, dec, Sin);
        chunk_out_kernel<<<dim3(NCH, 128, 2), 128, S3_SMEM>>>(
            xc0, xc1, zx0, zx1, dt0, dt1,
            m_Alog + i * 2 * NHEADS, m_D + i * 2 * NHEADS, Sin, y0, y1);

        rmsnorm_kernel<<<dim3(ML, 2), 256>>>(y0, y1, m_norm + (size_t)i * 2 * DINNER);

        tf32gemm<<<dim3(4, ML / 128, 2), 256, GEMM_SMEM>>>(
            y0, y1, Wo0, Wo1, nullptr, cb, cb + HDIM,
            ML, HDIM, DINNER, DINNER, lens, 0, 1);

        tf32gemm<<<dim3(4, ML / 128, 1), 256, GEMM_SMEM>>>(
            cb, nullptr, blk_Wo + (size_t)i * HDIM * DINNER, nullptr,
            blk_bo + i * HDIM, ot, nullptr,
            ML, HDIM, DINNER, HDIM, nullptr, 0, 0);
        addln_kernel<<<ML, 128>>>(ot, h, ln_g + i * HDIM, ln_b + i * HDIM);
    }

    tf32gemm<<<dim3(8, ML / 128, 1), 256, GEMM_SMEM>>>(
        h, nullptr, W_enc, nullptr, b_enc, outp, nullptr,
        ML, 2 * HDIM, HDIM, 2 * HDIM, nullptr, 0, 0);

    pool_kernel<<<BATCH * 32, 256>>>(outp, lens, pl);
    adapter_kernel<<<(BATCH * HDIM) / 8, 256>>>(pl, W_ad, b_ad,
                                                outp + (size_t)ML * 2 * HDIM);
}